// round 1
// baseline (speedup 1.0000x reference)
#include <cuda_runtime.h>
#include <math.h>

#define SEQ   4096
#define HDIM  4096
#define INNER 4096
#define NH    32
#define HD    128
#define BLK   256
#define NB    16            // SEQ / BLK
#define QKVW  12288         // 3 * INNER
#define EPS_RMS 1e-5f

// ---------------- scratch (static device allocations; no cudaMalloc) ----------------
__device__ float g_qkv[(size_t)SEQ * QKVW];       // 201 MB: silu(x @ w_qkv^T)
__device__ float g_hidden[(size_t)SEQ * INNER];   // 67 MB : attention output
__device__ float g_gate[(size_t)SEQ * INNER];     // 67 MB : sigmoid(x@w_gate^T) then gate*normed
__device__ float g_S[(size_t)NH * NB * HD * HD];  // 33 MB : per-block KV contributions
__device__ float g_kvst[(size_t)NH * NB * HD * HD]; // 33 MB: KV state BEFORE each block

// ---------------- epilogues ----------------
#define EPI_NONE 0
#define EPI_SILU 1
#define EPI_SIGM 2

template <int EPI>
__device__ __forceinline__ float epi(float v) {
    if (EPI == EPI_SILU) return v / (1.0f + expf(-v));
    if (EPI == EPI_SIGM) return 1.0f / (1.0f + expf(-v));
    return v;
}

// ---------------- fp32 SGEMM, C[m][n] = epi( sum_k A[m][k] * B[n][k] ) ----------------
// A: M x K row-major, B: N x K row-major (NT gemm), C: M x N row-major.
// 128x128 tile, BK=8, 256 threads, 8x8 per thread, double-buffered smem.
template <int EPI>
__global__ __launch_bounds__(256)
void sgemm_nt(const float* __restrict__ A, const float* __restrict__ B,
              float* __restrict__ C, int M, int N, int K)
{
    __shared__ float As[2][8][132];
    __shared__ float Bs[2][8][132];

    const int t    = threadIdx.x;
    const int bm   = blockIdx.y * 128;
    const int bn   = blockIdx.x * 128;
    const int arow = t >> 1;
    const int acol = (t & 1) * 4;
    const int ty   = t >> 4;
    const int tx   = t & 15;
    const int m0   = ty * 8;
    const int n0   = tx * 8;

    const float* Ap = A + (size_t)(bm + arow) * K + acol;
    const float* Bp = B + (size_t)(bn + arow) * K + acol;

    float acc[8][8];
#pragma unroll
    for (int i = 0; i < 8; ++i)
#pragma unroll
        for (int j = 0; j < 8; ++j) acc[i][j] = 0.0f;

    const int ntiles = K >> 3;

    float4 a = *(const float4*)Ap;
    float4 b = *(const float4*)Bp;
    int buf = 0;
    As[0][acol + 0][arow] = a.x; As[0][acol + 1][arow] = a.y;
    As[0][acol + 2][arow] = a.z; As[0][acol + 3][arow] = a.w;
    Bs[0][acol + 0][arow] = b.x; Bs[0][acol + 1][arow] = b.y;
    Bs[0][acol + 2][arow] = b.z; Bs[0][acol + 3][arow] = b.w;
    __syncthreads();

    for (int tt = 1; tt <= ntiles; ++tt) {
        float4 an, bn4;
        if (tt < ntiles) {
            an  = *(const float4*)(Ap + tt * 8);
            bn4 = *(const float4*)(Bp + tt * 8);
        }
#pragma unroll
        for (int kk = 0; kk < 8; ++kk) {
            float4 a0 = *(const float4*)&As[buf][kk][m0];
            float4 a1 = *(const float4*)&As[buf][kk][m0 + 4];
            float4 b0 = *(const float4*)&Bs[buf][kk][n0];
            float4 b1 = *(const float4*)&Bs[buf][kk][n0 + 4];
            float av[8] = {a0.x, a0.y, a0.z, a0.w, a1.x, a1.y, a1.z, a1.w};
            float bv[8] = {b0.x, b0.y, b0.z, b0.w, b1.x, b1.y, b1.z, b1.w};
#pragma unroll
            for (int i = 0; i < 8; ++i)
#pragma unroll
                for (int j = 0; j < 8; ++j) acc[i][j] += av[i] * bv[j];
        }
        if (tt < ntiles) {
            int nb = buf ^ 1;
            As[nb][acol + 0][arow] = an.x;  As[nb][acol + 1][arow] = an.y;
            As[nb][acol + 2][arow] = an.z;  As[nb][acol + 3][arow] = an.w;
            Bs[nb][acol + 0][arow] = bn4.x; Bs[nb][acol + 1][arow] = bn4.y;
            Bs[nb][acol + 2][arow] = bn4.z; Bs[nb][acol + 3][arow] = bn4.w;
            __syncthreads();
            buf = nb;
        }
    }

#pragma unroll
    for (int i = 0; i < 8; ++i) {
        float* Cp = C + (size_t)(bm + m0 + i) * N + bn + n0;
        float4 o0 = make_float4(epi<EPI>(acc[i][0]), epi<EPI>(acc[i][1]),
                                epi<EPI>(acc[i][2]), epi<EPI>(acc[i][3]));
        float4 o1 = make_float4(epi<EPI>(acc[i][4]), epi<EPI>(acc[i][5]),
                                epi<EPI>(acc[i][6]), epi<EPI>(acc[i][7]));
        *(float4*)Cp       = o0;
        *(float4*)(Cp + 4) = o1;
    }
}

// ---------------- attention stage A: S[h][b][d][e] = sum_i k'[i,d]*v[i,e] ----------------
// k'[i,d] = k[i,d] * exp(-s*(255-i));  i over 256 block rows.
__global__ __launch_bounds__(256)
void attn_kvblocks(const float* __restrict__ slope)
{
    const int b = blockIdx.x;
    const int h = blockIdx.y;
    const float s = slope[h];

    __shared__ float Ks[8][128];
    __shared__ float Vs[8][128];

    const int t  = threadIdx.x;
    const int ty = t >> 4, tx = t & 15;
    const int d0 = ty * 8, e0 = tx * 8;
    const int il = t >> 5;            // 0..7 row-in-chunk
    const int c4 = (t & 31) * 4;      // 0..124

    const float* kbase = g_qkv + (size_t)(b * BLK) * QKVW + h * 384 + 128;
    const float* vbase = kbase + 128;

    float acc[8][8];
#pragma unroll
    for (int i = 0; i < 8; ++i)
#pragma unroll
        for (int j = 0; j < 8; ++j) acc[i][j] = 0.0f;

    for (int ic = 0; ic < 32; ++ic) {
        const int i = ic * 8 + il;
        const float kd = expf(-s * (float)(255 - i));
        float4 k4 = *(const float4*)(kbase + (size_t)i * QKVW + c4);
        float4 v4 = *(const float4*)(vbase + (size_t)i * QKVW + c4);
        __syncthreads();
        Ks[il][c4 + 0] = k4.x * kd; Ks[il][c4 + 1] = k4.y * kd;
        Ks[il][c4 + 2] = k4.z * kd; Ks[il][c4 + 3] = k4.w * kd;
        *(float4*)&Vs[il][c4] = v4;
        __syncthreads();
#pragma unroll
        for (int ii = 0; ii < 8; ++ii) {
            float4 a0 = *(const float4*)&Ks[ii][d0];
            float4 a1 = *(const float4*)&Ks[ii][d0 + 4];
            float4 b0 = *(const float4*)&Vs[ii][e0];
            float4 b1 = *(const float4*)&Vs[ii][e0 + 4];
            float av[8] = {a0.x, a0.y, a0.z, a0.w, a1.x, a1.y, a1.z, a1.w};
            float bv[8] = {b0.x, b0.y, b0.z, b0.w, b1.x, b1.y, b1.z, b1.w};
#pragma unroll
            for (int i2 = 0; i2 < 8; ++i2)
#pragma unroll
                for (int j = 0; j < 8; ++j) acc[i2][j] += av[i2] * bv[j];
        }
    }

    float* Sp = g_S + (size_t)(h * NB + b) * HD * HD;
#pragma unroll
    for (int i = 0; i < 8; ++i) {
        *(float4*)&Sp[(size_t)(d0 + i) * HD + e0]     = make_float4(acc[i][0], acc[i][1], acc[i][2], acc[i][3]);
        *(float4*)&Sp[(size_t)(d0 + i) * HD + e0 + 4] = make_float4(acc[i][4], acc[i][5], acc[i][6], acc[i][7]);
    }
}

// ---------------- attention stage B: parallel scan of KV states ----------------
// kvst[h][b] = state BEFORE block b.  kvst[h][0] = kv_cache[h].
__global__ void attn_scan(const float* __restrict__ kv_cache, const float* __restrict__ slope)
{
    const int g = blockIdx.x * 256 + threadIdx.x;   // 32 * 16384 lanes
    const int h = g >> 14;
    const int e = g & 16383;
    const float dec = expf(-slope[h] * 256.0f);
    float c = kv_cache[(size_t)h * 16384 + e];
    const size_t base = (size_t)h * NB * 16384 + e;
#pragma unroll
    for (int b = 0; b < NB; ++b) {
        g_kvst[base + (size_t)b * 16384] = c;
        c = dec * c + g_S[base + (size_t)b * 16384];
    }
}

// ---------------- attention stage C1: o_inter = (q .* qdec) @ kvst ----------------
// 512 threads; output 256x128 per (b,h); writes g_hidden (initializing it).
__global__ __launch_bounds__(512)
void attn_ointer(const float* __restrict__ slope)
{
    const int b = blockIdx.x;
    const int h = blockIdx.y;
    const float s = slope[h];

    __shared__ float Qs[8][260];
    __shared__ float Ss[8][128];

    const int t  = threadIdx.x;
    const int ty = t >> 4;            // 0..31 -> m
    const int tx = t & 15;            // 0..15 -> e
    const int m0 = ty * 8, e0 = tx * 8;

    const int lm  = t >> 1;           // 0..255 load row
    const int ld4 = (t & 1) * 4;
    const float qd = expf(-s * (float)(lm + 1));
    const int sd  = t >> 5;           // 0..15 (used when t<256 -> 0..7)
    const int se4 = (t & 31) * 4;

    const float* qbase = g_qkv + (size_t)(b * BLK) * QKVW + h * 384;
    const float* st    = g_kvst + (size_t)(h * NB + b) * HD * HD;

    float acc[8][8];
#pragma unroll
    for (int i = 0; i < 8; ++i)
#pragma unroll
        for (int j = 0; j < 8; ++j) acc[i][j] = 0.0f;

    for (int dc = 0; dc < 16; ++dc) {
        const int d0 = dc * 8;
        float4 q4 = *(const float4*)(qbase + (size_t)lm * QKVW + d0 + ld4);
        float4 s4 = make_float4(0.f, 0.f, 0.f, 0.f);
        if (t < 256) s4 = *(const float4*)(st + (size_t)(d0 + sd) * HD + se4);
        __syncthreads();
        Qs[ld4 + 0][lm] = q4.x * qd; Qs[ld4 + 1][lm] = q4.y * qd;
        Qs[ld4 + 2][lm] = q4.z * qd; Qs[ld4 + 3][lm] = q4.w * qd;
        if (t < 256) *(float4*)&Ss[sd][se4] = s4;
        __syncthreads();
#pragma unroll
        for (int kk = 0; kk < 8; ++kk) {
            float4 a0 = *(const float4*)&Qs[kk][m0];
            float4 a1 = *(const float4*)&Qs[kk][m0 + 4];
            float4 b0 = *(const float4*)&Ss[kk][e0];
            float4 b1 = *(const float4*)&Ss[kk][e0 + 4];
            float av[8] = {a0.x, a0.y, a0.z, a0.w, a1.x, a1.y, a1.z, a1.w};
            float bv[8] = {b0.x, b0.y, b0.z, b0.w, b1.x, b1.y, b1.z, b1.w};
#pragma unroll
            for (int i = 0; i < 8; ++i)
#pragma unroll
                for (int j = 0; j < 8; ++j) acc[i][j] += av[i] * bv[j];
        }
    }

    float* hbase = g_hidden + (size_t)(b * BLK) * INNER + h * HD;
#pragma unroll
    for (int i = 0; i < 8; ++i) {
        float* Hp = hbase + (size_t)(m0 + i) * INNER + e0;
        *(float4*)Hp       = make_float4(acc[i][0], acc[i][1], acc[i][2], acc[i][3]);
        *(float4*)(Hp + 4) = make_float4(acc[i][4], acc[i][5], acc[i][6], acc[i][7]);
    }
}

// ---------------- attention stage C2: o_intra += masked-decayed (q k^T) v ----------------
// grid (mt=8, b=16, h=32); 32 m-rows x 128 e per CTA; causal n-chunks of 32.
__global__ __launch_bounds__(256)
void attn_ointra(const float* __restrict__ slope)
{
    const int mt = blockIdx.x;    // 0..7
    const int b  = blockIdx.y;
    const int h  = blockIdx.z;
    const float s = slope[h];

    __shared__ float Qs[32][132];
    __shared__ float KVs[32][132];
    __shared__ float Ps[32][36];

    const int t = threadIdx.x;
    const float* qbase = g_qkv + (size_t)(b * BLK) * QKVW + h * 384;

    // load Q tile (no decay): rows mt*32 .. mt*32+31
#pragma unroll
    for (int r = 0; r < 4; ++r) {
        int idx = t + r * 256;
        int mm = idx >> 5, d4 = (idx & 31) * 4;
        float4 q4 = *(const float4*)(qbase + (size_t)(mt * 32 + mm) * QKVW + d4);
        *(float4*)&Qs[mm][d4] = q4;
    }

    const int p_ty = t >> 4, p_tx = t & 15;
    const int pm0  = p_ty * 2;
    const int om0  = p_ty * 2;
    const int e0   = p_tx * 8;

    float oacc[2][8];
#pragma unroll
    for (int i = 0; i < 2; ++i)
#pragma unroll
        for (int j = 0; j < 8; ++j) oacc[i][j] = 0.0f;

    for (int nt = 0; nt <= mt; ++nt) {
        __syncthreads();   // previous O-phase done reading KVs; Q stores visible (first iter)
#pragma unroll
        for (int r = 0; r < 4; ++r) {
            int idx = t + r * 256;
            int nn = idx >> 5, d4 = (idx & 31) * 4;
            float4 k4 = *(const float4*)(qbase + 128 + (size_t)(nt * 32 + nn) * QKVW + d4);
            *(float4*)&KVs[nn][d4] = k4;
        }
        __syncthreads();

        float p00 = 0.f, p01 = 0.f, p10 = 0.f, p11 = 0.f;
#pragma unroll 4
        for (int d = 0; d < 128; ++d) {
            float a0 = Qs[pm0][d], a1 = Qs[pm0 + 1][d];
            float b0 = KVs[p_tx][d], b1 = KVs[p_tx + 16][d];
            p00 += a0 * b0; p01 += a0 * b1;
            p10 += a1 * b0; p11 += a1 * b1;
        }
        const int mg0 = mt * 32 + pm0, mg1 = mg0 + 1;
        const int ng0 = nt * 32 + p_tx, ng1 = nt * 32 + p_tx + 16;
        Ps[pm0][p_tx]          = (mg0 >= ng0) ? p00 * expf(-s * (float)(mg0 - ng0)) : 0.0f;
        Ps[pm0][p_tx + 16]     = (mg0 >= ng1) ? p01 * expf(-s * (float)(mg0 - ng1)) : 0.0f;
        Ps[pm0 + 1][p_tx]      = (mg1 >= ng0) ? p10 * expf(-s * (float)(mg1 - ng0)) : 0.0f;
        Ps[pm0 + 1][p_tx + 16] = (mg1 >= ng1) ? p11 * expf(-s * (float)(mg1 - ng1)) : 0.0f;
        __syncthreads();

        // load V chunk over KVs
#pragma unroll
        for (int r = 0; r < 4; ++r) {
            int idx = t + r * 256;
            int nn = idx >> 5, d4 = (idx & 31) * 4;
            float4 v4 = *(const float4*)(qbase + 256 + (size_t)(nt * 32 + nn) * QKVW + d4);
            *(float4*)&KVs[nn][d4] = v4;
        }
        __syncthreads();

#pragma unroll 4
        for (int n = 0; n < 32; ++n) {
            float a0 = Ps[om0][n], a1 = Ps[om0 + 1][n];
            float4 v0 = *(const float4*)&KVs[n][e0];
            float4 v1 = *(const float4*)&KVs[n][e0 + 4];
            oacc[0][0] += a0 * v0.x; oacc[0][1] += a0 * v0.y;
            oacc[0][2] += a0 * v0.z; oacc[0][3] += a0 * v0.w;
            oacc[0][4] += a0 * v1.x; oacc[0][5] += a0 * v1.y;
            oacc[0][6] += a0 * v1.z; oacc[0][7] += a0 * v1.w;
            oacc[1][0] += a1 * v0.x; oacc[1][1] += a1 * v0.y;
            oacc[1][2] += a1 * v0.z; oacc[1][3] += a1 * v0.w;
            oacc[1][4] += a1 * v1.x; oacc[1][5] += a1 * v1.y;
            oacc[1][6] += a1 * v1.z; oacc[1][7] += a1 * v1.w;
        }
    }

    // accumulate into hidden (o_inter already there)
    float* hbase = g_hidden + (size_t)(b * BLK + mt * 32) * INNER + h * HD;
#pragma unroll
    for (int i = 0; i < 2; ++i) {
        float* Hp = hbase + (size_t)(om0 + i) * INNER + e0;
        float4 o0 = *(float4*)Hp;
        float4 o1 = *(float4*)(Hp + 4);
        o0.x += oacc[i][0]; o0.y += oacc[i][1]; o0.z += oacc[i][2]; o0.w += oacc[i][3];
        o1.x += oacc[i][4]; o1.y += oacc[i][5]; o1.z += oacc[i][6]; o1.w += oacc[i][7];
        *(float4*)Hp       = o0;
        *(float4*)(Hp + 4) = o1;
    }
}

// ---------------- RMSNorm * norm_weight * gate (in place into g_gate) ----------------
__global__ __launch_bounds__(256)
void rmsnorm_gate(const float* __restrict__ nw)
{
    const int m = blockIdx.x;
    const int t = threadIdx.x;
    const float* hrow = g_hidden + (size_t)m * INNER;
    float* grow = g_gate + (size_t)m * INNER;

    float ss = 0.0f;
    for (int i = t; i < INNER / 4; i += 256) {
        float4 h4 = *(const float4*)(hrow + i * 4);
        ss += h4.x * h4.x + h4.y * h4.y + h4.z * h4.z + h4.w * h4.w;
    }
    __shared__ float red[256];
    red[t] = ss;
    __syncthreads();
    for (int s2 = 128; s2 > 0; s2 >>= 1) {
        if (t < s2) red[t] += red[t + s2];
        __syncthreads();
    }
    const float rs = rsqrtf(red[0] / (float)INNER + EPS_RMS);

    for (int i = t; i < INNER / 4; i += 256) {
        float4 h4 = *(const float4*)(hrow + i * 4);
        float4 g4 = *(const float4*)(grow + i * 4);
        float4 w4 = *(const float4*)(nw + i * 4);
        float4 o;
        o.x = g4.x * (h4.x * rs * w4.x);
        o.y = g4.y * (h4.y * rs * w4.y);
        o.z = g4.z * (h4.z * rs * w4.z);
        o.w = g4.w * (h4.w * rs * w4.w);
        *(float4*)(grow + i * 4) = o;
    }
}

// ---------------- launcher ----------------
extern "C" void kernel_launch(void* const* d_in, const int* in_sizes, int n_in,
                              void* d_out, int out_size)
{
    (void)in_sizes; (void)n_in; (void)out_size;
    const float* x     = (const float*)d_in[0];
    const float* wqkv  = (const float*)d_in[1];
    const float* wgate = (const float*)d_in[2];
    const float* wout  = (const float*)d_in[3];
    const float* nw    = (const float*)d_in[4];
    const float* kvc   = (const float*)d_in[5];
    const float* slope = (const float*)d_in[6];
    float* out = (float*)d_out;

    float *p_qkv = nullptr, *p_gate = nullptr;
    cudaGetSymbolAddress((void**)&p_qkv, g_qkv);
    cudaGetSymbolAddress((void**)&p_gate, g_gate);

    // qkv = silu(x @ w_qkv^T)   [4096 x 12288]
    sgemm_nt<EPI_SILU><<<dim3(QKVW / 128, SEQ / 128), 256>>>(x, wqkv, p_qkv, SEQ, QKVW, HDIM);
    // gate = sigmoid(x @ w_gate^T)  [4096 x 4096]
    sgemm_nt<EPI_SIGM><<<dim3(INNER / 128, SEQ / 128), 256>>>(x, wgate, p_gate, SEQ, INNER, HDIM);

    // lightning attention
    attn_kvblocks<<<dim3(NB, NH), 256>>>(slope);
    attn_scan<<<(NH * HD * HD) / 256, 256>>>(kvc, slope);
    attn_ointer<<<dim3(NB, NH), 512>>>(slope);
    attn_ointra<<<dim3(8, NB, NH), 256>>>(slope);

    // rmsnorm * weight * gate
    rmsnorm_gate<<<SEQ, 256>>>(nw);

    // out = (gate * normed) @ w_out^T
    sgemm_nt<EPI_NONE><<<dim3(HDIM / 128, SEQ / 128), 256>>>(p_gate, wout, out, SEQ, HDIM, INNER);
}

// round 3
// speedup vs baseline: 3.1412x; 3.1412x over previous
#include <cuda_runtime.h>
#include <math.h>
#include <stdint.h>

#define SEQ   4096
#define HDIM  4096
#define INNER 4096
#define NH    32
#define HD    128
#define BLK   256
#define NB    16
#define QKVW  12288
#define EPS_RMS 1e-5f

#define GK    4096          // shared K dim of all three GEMMs
#define BM    128
#define BN    128
#define BK    32
#define KTILES (GK / BK)    // 128
#define KPAD  36            // 32 + 4 floats pad
#define STG_F (128 * KPAD)  // floats per operand per stage (4608)
#define STG_B (STG_F * 4)   // 18432 bytes
#define STAGE_BYTES (2 * STG_B)     // A + B = 36864
#define NSTG  3
#define GEMM_SMEM (NSTG * STAGE_BYTES)   // 110592

// ---------------- scratch ----------------
__device__ float g_qkv[(size_t)SEQ * QKVW];
__device__ float g_hidden[(size_t)SEQ * INNER];
__device__ float g_gate[(size_t)SEQ * INNER];
__device__ float g_S[(size_t)NH * NB * HD * HD];
__device__ float g_kvst[(size_t)NH * NB * HD * HD];
__device__ float g_xt[(size_t)SEQ * HDIM];
__device__ float g_wqkvt[(size_t)QKVW * HDIM];
__device__ float g_wgatet[(size_t)INNER * HDIM];
__device__ float g_woutt[(size_t)HDIM * INNER];

// ---------------- helpers ----------------
__device__ __forceinline__ uint32_t smem_u32(const void* p) {
    uint32_t a;
    asm("{ .reg .u64 t; cvta.to.shared.u64 t, %1; cvt.u32.u64 %0, t; }" : "=r"(a) : "l"(p));
    return a;
}

__device__ __forceinline__ void cp_async16(uint32_t dst, const void* src) {
    asm volatile("cp.async.cg.shared.global [%0], [%1], 16;" :: "r"(dst), "l"(src));
}
#define CP_COMMIT() asm volatile("cp.async.commit_group;" ::: "memory")
#define CP_WAIT(n)  asm volatile("cp.async.wait_group %0;" :: "n"(n) : "memory")

__device__ __forceinline__ void mma_tf32(float* c, const uint32_t* a, const uint32_t* b) {
    asm volatile(
        "mma.sync.aligned.m16n8k8.row.col.f32.tf32.tf32.f32 "
        "{%0,%1,%2,%3}, {%4,%5,%6,%7}, {%8,%9}, {%0,%1,%2,%3};"
        : "+f"(c[0]), "+f"(c[1]), "+f"(c[2]), "+f"(c[3])
        : "r"(a[0]), "r"(a[1]), "r"(a[2]), "r"(a[3]), "r"(b[0]), "r"(b[1]));
}

#define EPI_NONE 0
#define EPI_SILU 1
#define EPI_SIGM 2
template <int EPI>
__device__ __forceinline__ float epi(float v) {
    if (EPI == EPI_SILU) return v / (1.0f + expf(-v));
    if (EPI == EPI_SIGM) return 1.0f / (1.0f + expf(-v));
    return v;
}

__device__ __forceinline__ float to_tf32(float f) {
    uint32_t u;
    asm("cvt.rna.tf32.f32 %0, %1;" : "=r"(u) : "f"(f));
    return __uint_as_float(u);
}

__global__ __launch_bounds__(256)
void cvt_tf32_kernel(const float* __restrict__ in, float* __restrict__ out, int n4) {
    int i = blockIdx.x * 256 + threadIdx.x;
    if (i < n4) {
        float4 v = ((const float4*)in)[i];
        v.x = to_tf32(v.x); v.y = to_tf32(v.y);
        v.z = to_tf32(v.z); v.w = to_tf32(v.w);
        ((float4*)out)[i] = v;
    }
}

// ---------------- tf32 mma.sync GEMM: C[m][n] = epi(sum_k A[m][k]*B[n][k]) ----------------
// A: M x GK row-major (tf32-rounded), B: Ntot x GK row-major (tf32-rounded), C: M x Ntot.
__device__ __forceinline__ void g_load_stage(uint32_t sbase, int slot, int s,
                                             const float* __restrict__ Ab,
                                             const float* __restrict__ Bb, int t)
{
    const uint32_t stA = sbase + slot * STAGE_BYTES;
    const uint32_t stB = stA + STG_B;
    const float* ga = Ab + (size_t)s * BK;
    const float* gb = Bb + (size_t)s * BK;
#pragma unroll
    for (int i = 0; i < 4; ++i) {
        int id = t + 256 * i;                 // 0..1023
        int row = id >> 3, c = id & 7;        // 128 rows x 8 float4
        cp_async16(stA + (row * KPAD + c * 4) * 4, ga + (size_t)row * GK + c * 4);
    }
#pragma unroll
    for (int i = 0; i < 4; ++i) {
        int id = t + 256 * i;
        int row = id >> 3, c = id & 7;
        cp_async16(stB + (row * KPAD + c * 4) * 4, gb + (size_t)row * GK + c * 4);
    }
}

template <int EPI>
__global__ __launch_bounds__(256, 1)
void gemm_mma(const float* __restrict__ A, const float* __restrict__ B,
              float* __restrict__ C, int Ntot)
{
    extern __shared__ __align__(128) float smem[];
    const uint32_t sbase = smem_u32(smem);
    const int t    = threadIdx.x;
    const int wid  = t >> 5;
    const int lane = t & 31;
    const int bm = blockIdx.y * BM;
    const int bn = blockIdx.x * BN;
    const float* Ab = A + (size_t)bm * GK;
    const float* Bb = B + (size_t)bn * GK;

    const int wm = (wid & 1) * 64;        // warp row offset in tile
    const int wn = (wid >> 1) * 32;       // warp col offset in tile
    const int r  = lane >> 2;             // 0..7
    const int kq = lane & 3;              // 0..3

    float c[4][4][4];
#pragma unroll
    for (int i = 0; i < 4; ++i)
#pragma unroll
        for (int j = 0; j < 4; ++j)
#pragma unroll
            for (int q = 0; q < 4; ++q) c[i][j][q] = 0.0f;

    // prologue: stages 0,1
    g_load_stage(sbase, 0, 0, Ab, Bb, t); CP_COMMIT();
    g_load_stage(sbase, 1, 1, Ab, Bb, t); CP_COMMIT();

    for (int s = 0; s < KTILES; ++s) {
        const int slot = s % NSTG;
        CP_WAIT(1);
        __syncthreads();

        if (s + 2 < KTILES) {
            g_load_stage(sbase, (s + 2) % NSTG, s + 2, Ab, Bb, t);
        }
        CP_COMMIT();

        const float* As = smem + slot * (STAGE_BYTES / 4);
        const float* Bs = As + STG_F;

#pragma unroll
        for (int ks = 0; ks < 4; ++ks) {
            const int k0 = ks * 8;
            uint32_t af[4][4], bf[4][2];
#pragma unroll
            for (int i = 0; i < 4; ++i) {
                const float* ap = As + (wm + i * 16 + r) * KPAD + k0 + kq;
                af[i][0] = __float_as_uint(ap[0]);
                af[i][1] = __float_as_uint(ap[8 * KPAD]);
                af[i][2] = __float_as_uint(ap[4]);
                af[i][3] = __float_as_uint(ap[8 * KPAD + 4]);
            }
#pragma unroll
            for (int j = 0; j < 4; ++j) {
                const float* bp = Bs + (wn + j * 8 + r) * KPAD + k0 + kq;
                bf[j][0] = __float_as_uint(bp[0]);
                bf[j][1] = __float_as_uint(bp[4]);
            }
#pragma unroll
            for (int i = 0; i < 4; ++i)
#pragma unroll
                for (int j = 0; j < 4; ++j)
                    mma_tf32(c[i][j], af[i], bf[j]);
        }
    }

    // epilogue
#pragma unroll
    for (int i = 0; i < 4; ++i) {
        const int row0 = bm + wm + i * 16 + r;
#pragma unroll
        for (int j = 0; j < 4; ++j) {
            const int col = bn + wn + j * 8 + 2 * kq;
            float2 v0 = make_float2(epi<EPI>(c[i][j][0]), epi<EPI>(c[i][j][1]));
            float2 v1 = make_float2(epi<EPI>(c[i][j][2]), epi<EPI>(c[i][j][3]));
            *(float2*)(C + (size_t)row0 * Ntot + col)       = v0;
            *(float2*)(C + (size_t)(row0 + 8) * Ntot + col) = v1;
        }
    }
}

// ---------------- attention stage A ----------------
__global__ __launch_bounds__(256)
void attn_kvblocks(const float* __restrict__ slope)
{
    const int b = blockIdx.x;
    const int h = blockIdx.y;
    const float s = slope[h];

    __shared__ float Ks[8][128];
    __shared__ float Vs[8][128];

    const int t  = threadIdx.x;
    const int ty = t >> 4, tx = t & 15;
    const int d0 = ty * 8, e0 = tx * 8;
    const int il = t >> 5;
    const int c4 = (t & 31) * 4;

    const float* kbase = g_qkv + (size_t)(b * BLK) * QKVW + h * 384 + 128;
    const float* vbase = kbase + 128;

    float acc[8][8];
#pragma unroll
    for (int i = 0; i < 8; ++i)
#pragma unroll
        for (int j = 0; j < 8; ++j) acc[i][j] = 0.0f;

    for (int ic = 0; ic < 32; ++ic) {
        const int i = ic * 8 + il;
        const float kd = expf(-s * (float)(255 - i));
        float4 k4 = *(const float4*)(kbase + (size_t)i * QKVW + c4);
        float4 v4 = *(const float4*)(vbase + (size_t)i * QKVW + c4);
        __syncthreads();
        Ks[il][c4 + 0] = k4.x * kd; Ks[il][c4 + 1] = k4.y * kd;
        Ks[il][c4 + 2] = k4.z * kd; Ks[il][c4 + 3] = k4.w * kd;
        *(float4*)&Vs[il][c4] = v4;
        __syncthreads();
#pragma unroll
        for (int ii = 0; ii < 8; ++ii) {
            float4 a0 = *(const float4*)&Ks[ii][d0];
            float4 a1 = *(const float4*)&Ks[ii][d0 + 4];
            float4 b0 = *(const float4*)&Vs[ii][e0];
            float4 b1 = *(const float4*)&Vs[ii][e0 + 4];
            float av[8] = {a0.x, a0.y, a0.z, a0.w, a1.x, a1.y, a1.z, a1.w};
            float bv[8] = {b0.x, b0.y, b0.z, b0.w, b1.x, b1.y, b1.z, b1.w};
#pragma unroll
            for (int i2 = 0; i2 < 8; ++i2)
#pragma unroll
                for (int j = 0; j < 8; ++j) acc[i2][j] += av[i2] * bv[j];
        }
    }

    float* Sp = g_S + (size_t)(h * NB + b) * HD * HD;
#pragma unroll
    for (int i = 0; i < 8; ++i) {
        *(float4*)&Sp[(size_t)(d0 + i) * HD + e0]     = make_float4(acc[i][0], acc[i][1], acc[i][2], acc[i][3]);
        *(float4*)&Sp[(size_t)(d0 + i) * HD + e0 + 4] = make_float4(acc[i][4], acc[i][5], acc[i][6], acc[i][7]);
    }
}

// ---------------- attention stage B ----------------
__global__ void attn_scan(const float* __restrict__ kv_cache, const float* __restrict__ slope)
{
    const int g = blockIdx.x * 256 + threadIdx.x;
    const int h = g >> 14;
    const int e = g & 16383;
    const float dec = expf(-slope[h] * 256.0f);
    float c = kv_cache[(size_t)h * 16384 + e];
    const size_t base = (size_t)h * NB * 16384 + e;
#pragma unroll
    for (int b = 0; b < NB; ++b) {
        g_kvst[base + (size_t)b * 16384] = c;
        c = dec * c + g_S[base + (size_t)b * 16384];
    }
}

// ---------------- attention stage C1 ----------------
__global__ __launch_bounds__(512)
void attn_ointer(const float* __restrict__ slope)
{
    const int b = blockIdx.x;
    const int h = blockIdx.y;
    const float s = slope[h];

    __shared__ float Qs[8][260];
    __shared__ float Ss[8][128];

    const int t  = threadIdx.x;
    const int ty = t >> 4;
    const int tx = t & 15;
    const int m0 = ty * 8, e0 = tx * 8;

    const int lm  = t >> 1;
    const int ld4 = (t & 1) * 4;
    const float qd = expf(-s * (float)(lm + 1));
    const int sd  = t >> 5;
    const int se4 = (t & 31) * 4;

    const float* qbase = g_qkv + (size_t)(b * BLK) * QKVW + h * 384;
    const float* st    = g_kvst + (size_t)(h * NB + b) * HD * HD;

    float acc[8][8];
#pragma unroll
    for (int i = 0; i < 8; ++i)
#pragma unroll
        for (int j = 0; j < 8; ++j) acc[i][j] = 0.0f;

    for (int dc = 0; dc < 16; ++dc) {
        const int d0 = dc * 8;
        float4 q4 = *(const float4*)(qbase + (size_t)lm * QKVW + d0 + ld4);
        float4 s4 = make_float4(0.f, 0.f, 0.f, 0.f);
        if (t < 256) s4 = *(const float4*)(st + (size_t)(d0 + sd) * HD + se4);
        __syncthreads();
        Qs[ld4 + 0][lm] = q4.x * qd; Qs[ld4 + 1][lm] = q4.y * qd;
        Qs[ld4 + 2][lm] = q4.z * qd; Qs[ld4 + 3][lm] = q4.w * qd;
        if (t < 256) *(float4*)&Ss[sd][se4] = s4;
        __syncthreads();
#pragma unroll
        for (int kk = 0; kk < 8; ++kk) {
            float4 a0 = *(const float4*)&Qs[kk][m0];
            float4 a1 = *(const float4*)&Qs[kk][m0 + 4];
            float4 b0 = *(const float4*)&Ss[kk][e0];
            float4 b1 = *(const float4*)&Ss[kk][e0 + 4];
            float av[8] = {a0.x, a0.y, a0.z, a0.w, a1.x, a1.y, a1.z, a1.w};
            float bv[8] = {b0.x, b0.y, b0.z, b0.w, b1.x, b1.y, b1.z, b1.w};
#pragma unroll
            for (int i = 0; i < 8; ++i)
#pragma unroll
                for (int j = 0; j < 8; ++j) acc[i][j] += av[i] * bv[j];
        }
    }

    float* hbase = g_hidden + (size_t)(b * BLK) * INNER + h * HD;
#pragma unroll
    for (int i = 0; i < 8; ++i) {
        float* Hp = hbase + (size_t)(m0 + i) * INNER + e0;
        *(float4*)Hp       = make_float4(acc[i][0], acc[i][1], acc[i][2], acc[i][3]);
        *(float4*)(Hp + 4) = make_float4(acc[i][4], acc[i][5], acc[i][6], acc[i][7]);
    }
}

// ---------------- attention stage C2 ----------------
__global__ __launch_bounds__(256)
void attn_ointra(const float* __restrict__ slope)
{
    const int mt = blockIdx.x;
    const int b  = blockIdx.y;
    const int h  = blockIdx.z;
    const float s = slope[h];

    __shared__ float Qs[32][132];
    __shared__ float KVs[32][132];
    __shared__ float Ps[32][36];

    const int t = threadIdx.x;
    const float* qbase = g_qkv + (size_t)(b * BLK) * QKVW + h * 384;

#pragma unroll
    for (int r = 0; r < 4; ++r) {
        int idx = t + r * 256;
        int mm = idx >> 5, d4 = (idx & 31) * 4;
        float4 q4 = *(const float4*)(qbase + (size_t)(mt * 32 + mm) * QKVW + d4);
        *(float4*)&Qs[mm][d4] = q4;
    }

    const int p_ty = t >> 4, p_tx = t & 15;
    const int pm0  = p_ty * 2;
    const int om0  = p_ty * 2;
    const int e0   = p_tx * 8;

    float oacc[2][8];
#pragma unroll
    for (int i = 0; i < 2; ++i)
#pragma unroll
        for (int j = 0; j < 8; ++j) oacc[i][j] = 0.0f;

    for (int nt = 0; nt <= mt; ++nt) {
        __syncthreads();
#pragma unroll
        for (int r = 0; r < 4; ++r) {
            int idx = t + r * 256;
            int nn = idx >> 5, d4 = (idx & 31) * 4;
            float4 k4 = *(const float4*)(qbase + 128 + (size_t)(nt * 32 + nn) * QKVW + d4);
            *(float4*)&KVs[nn][d4] = k4;
        }
        __syncthreads();

        float p00 = 0.f, p01 = 0.f, p10 = 0.f, p11 = 0.f;
#pragma unroll 4
        for (int d = 0; d < 128; ++d) {
            float a0 = Qs[pm0][d], a1 = Qs[pm0 + 1][d];
            float b0 = KVs[p_tx][d], b1 = KVs[p_tx + 16][d];
            p00 += a0 * b0; p01 += a0 * b1;
            p10 += a1 * b0; p11 += a1 * b1;
        }
        const int mg0 = mt * 32 + pm0, mg1 = mg0 + 1;
        const int ng0 = nt * 32 + p_tx, ng1 = nt * 32 + p_tx + 16;
        Ps[pm0][p_tx]          = (mg0 >= ng0) ? p00 * expf(-s * (float)(mg0 - ng0)) : 0.0f;
        Ps[pm0][p_tx + 16]     = (mg0 >= ng1) ? p01 * expf(-s * (float)(mg0 - ng1)) : 0.0f;
        Ps[pm0 + 1][p_tx]      = (mg1 >= ng0) ? p10 * expf(-s * (float)(mg1 - ng0)) : 0.0f;
        Ps[pm0 + 1][p_tx + 16] = (mg1 >= ng1) ? p11 * expf(-s * (float)(mg1 - ng1)) : 0.0f;
        __syncthreads();

#pragma unroll
        for (int r = 0; r < 4; ++r) {
            int idx = t + r * 256;
            int nn = idx >> 5, d4 = (idx & 31) * 4;
            float4 v4 = *(const float4*)(qbase + 256 + (size_t)(nt * 32 + nn) * QKVW + d4);
            *(float4*)&KVs[nn][d4] = v4;
        }
        __syncthreads();

#pragma unroll 4
        for (int n = 0; n < 32; ++n) {
            float a0 = Ps[om0][n], a1 = Ps[om0 + 1][n];
            float4 v0 = *(const float4*)&KVs[n][e0];
            float4 v1 = *(const float4*)&KVs[n][e0 + 4];
            oacc[0][0] += a0 * v0.x; oacc[0][1] += a0 * v0.y;
            oacc[0][2] += a0 * v0.z; oacc[0][3] += a0 * v0.w;
            oacc[0][4] += a0 * v1.x; oacc[0][5] += a0 * v1.y;
            oacc[0][6] += a0 * v1.z; oacc[0][7] += a0 * v1.w;
            oacc[1][0] += a1 * v0.x; oacc[1][1] += a1 * v0.y;
            oacc[1][2] += a1 * v0.z; oacc[1][3] += a1 * v0.w;
            oacc[1][4] += a1 * v1.x; oacc[1][5] += a1 * v1.y;
            oacc[1][6] += a1 * v1.z; oacc[1][7] += a1 * v1.w;
        }
    }

    float* hbase = g_hidden + (size_t)(b * BLK + mt * 32) * INNER + h * HD;
#pragma unroll
    for (int i = 0; i < 2; ++i) {
        float* Hp = hbase + (size_t)(om0 + i) * INNER + e0;
        float4 o0 = *(float4*)Hp;
        float4 o1 = *(float4*)(Hp + 4);
        o0.x += oacc[i][0]; o0.y += oacc[i][1]; o0.z += oacc[i][2]; o0.w += oacc[i][3];
        o1.x += oacc[i][4]; o1.y += oacc[i][5]; o1.z += oacc[i][6]; o1.w += oacc[i][7];
        *(float4*)Hp       = o0;
        *(float4*)(Hp + 4) = o1;
    }
}

// ---------------- RMSNorm * weight * gate -> tf32-rounded (in place into g_gate) ----------------
__global__ __launch_bounds__(256)
void rmsnorm_gate(const float* __restrict__ nw)
{
    const int m = blockIdx.x;
    const int t = threadIdx.x;
    const float* hrow = g_hidden + (size_t)m * INNER;
    float* grow = g_gate + (size_t)m * INNER;

    float ss = 0.0f;
    for (int i = t; i < INNER / 4; i += 256) {
        float4 h4 = *(const float4*)(hrow + i * 4);
        ss += h4.x * h4.x + h4.y * h4.y + h4.z * h4.z + h4.w * h4.w;
    }
    __shared__ float red[256];
    red[t] = ss;
    __syncthreads();
    for (int s2 = 128; s2 > 0; s2 >>= 1) {
        if (t < s2) red[t] += red[t + s2];
        __syncthreads();
    }
    const float rs = rsqrtf(red[0] / (float)INNER + EPS_RMS);

    for (int i = t; i < INNER / 4; i += 256) {
        float4 h4 = *(const float4*)(hrow + i * 4);
        float4 g4 = *(const float4*)(grow + i * 4);
        float4 w4 = *(const float4*)(nw + i * 4);
        float4 o;
        o.x = to_tf32(g4.x * (h4.x * rs * w4.x));
        o.y = to_tf32(g4.y * (h4.y * rs * w4.y));
        o.z = to_tf32(g4.z * (h4.z * rs * w4.z));
        o.w = to_tf32(g4.w * (h4.w * rs * w4.w));
        *(float4*)(grow + i * 4) = o;
    }
}

// ---------------- launcher ----------------
extern "C" void kernel_launch(void* const* d_in, const int* in_sizes, int n_in,
                              void* d_out, int out_size)
{
    (void)in_sizes; (void)n_in; (void)out_size;
    const float* x     = (const float*)d_in[0];
    const float* wqkv  = (const float*)d_in[1];
    const float* wgate = (const float*)d_in[2];
    const float* wout  = (const float*)d_in[3];
    const float* nw    = (const float*)d_in[4];
    const float* kvc   = (const float*)d_in[5];
    const float* slope = (const float*)d_in[6];
    float* out = (float*)d_out;

    float *p_qkv = nullptr, *p_gate = nullptr, *p_xt = nullptr,
          *p_wqkvt = nullptr, *p_wgatet = nullptr, *p_woutt = nullptr;
    cudaGetSymbolAddress((void**)&p_qkv, g_qkv);
    cudaGetSymbolAddress((void**)&p_gate, g_gate);
    cudaGetSymbolAddress((void**)&p_xt, g_xt);
    cudaGetSymbolAddress((void**)&p_wqkvt, g_wqkvt);
    cudaGetSymbolAddress((void**)&p_wgatet, g_wgatet);
    cudaGetSymbolAddress((void**)&p_woutt, g_woutt);

    cudaFuncSetAttribute(gemm_mma<EPI_SILU>, cudaFuncAttributeMaxDynamicSharedMemorySize, GEMM_SMEM);
    cudaFuncSetAttribute(gemm_mma<EPI_SIGM>, cudaFuncAttributeMaxDynamicSharedMemorySize, GEMM_SMEM);
    cudaFuncSetAttribute(gemm_mma<EPI_NONE>, cudaFuncAttributeMaxDynamicSharedMemorySize, GEMM_SMEM);

    // tf32-round inputs
    cvt_tf32_kernel<<<(SEQ * HDIM / 4 + 255) / 256, 256>>>(x, p_xt, SEQ * HDIM / 4);
    cvt_tf32_kernel<<<(QKVW * HDIM / 4 + 255) / 256, 256>>>(wqkv, p_wqkvt, QKVW * HDIM / 4);
    cvt_tf32_kernel<<<(INNER * HDIM / 4 + 255) / 256, 256>>>(wgate, p_wgatet, INNER * HDIM / 4);
    cvt_tf32_kernel<<<(HDIM * INNER / 4 + 255) / 256, 256>>>(wout, p_woutt, HDIM * INNER / 4);

    // qkv = silu(x @ w_qkv^T)
    gemm_mma<EPI_SILU><<<dim3(QKVW / BN, SEQ / BM), 256, GEMM_SMEM>>>(p_xt, p_wqkvt, p_qkv, QKVW);
    // gate = sigmoid(x @ w_gate^T)
    gemm_mma<EPI_SIGM><<<dim3(INNER / BN, SEQ / BM), 256, GEMM_SMEM>>>(p_xt, p_wgatet, p_gate, INNER);

    // lightning attention (fp32)
    attn_kvblocks<<<dim3(NB, NH), 256>>>(slope);
    attn_scan<<<(NH * HD * HD) / 256, 256>>>(kvc, slope);
    attn_ointer<<<dim3(NB, NH), 512>>>(slope);
    attn_ointra<<<dim3(8, NB, NH), 256>>>(slope);

    // rmsnorm * weight * gate (tf32-rounded output)
    rmsnorm_gate<<<SEQ, 256>>>(nw);

    // out = (gate * normed) @ w_out^T
    gemm_mma<EPI_NONE><<<dim3(HDIM / BN, SEQ / BM), 256, GEMM_SMEM>>>(p_gate, p_woutt, out, HDIM);
}

// round 4
// speedup vs baseline: 3.3275x; 1.0593x over previous
#include <cuda_runtime.h>
#include <math.h>
#include <stdint.h>

#define SEQ   4096
#define HDIM  4096
#define INNER 4096
#define NH    32
#define HD    128
#define BLK   256
#define NB    16
#define QKVW  12288
#define EPS_RMS 1e-5f

#define GK    4096          // shared K dim of all three GEMMs
#define BM    128
#define BN    256
#define BK    32
#define KTILES (GK / BK)    // 128
#define KPAD  36            // 32 + 4 floats pad
#define STG_FA (128 * KPAD)             // A floats per stage (4608)
#define STG_FB (256 * KPAD)             // B floats per stage (9216)
#define STG_BA (STG_FA * 4)             // 18432 bytes
#define STAGE_BYTES ((STG_FA + STG_FB) * 4)   // 55296
#define NSTG  3
#define GEMM_SMEM (NSTG * STAGE_BYTES)  // 165888

// ---------------- scratch ----------------
__device__ float g_qkv[(size_t)SEQ * QKVW];
__device__ float g_hidden[(size_t)SEQ * INNER];
__device__ float g_gate[(size_t)SEQ * INNER];
__device__ float g_S[(size_t)NH * NB * HD * HD];
__device__ float g_kvst[(size_t)NH * NB * HD * HD];
__device__ float g_xt[(size_t)SEQ * HDIM];
__device__ float g_wqkvt[(size_t)QKVW * HDIM];
__device__ float g_wgatet[(size_t)INNER * HDIM];
__device__ float g_woutt[(size_t)HDIM * INNER];

// ---------------- helpers ----------------
__device__ __forceinline__ uint32_t smem_u32(const void* p) {
    uint32_t a;
    asm("{ .reg .u64 t; cvta.to.shared.u64 t, %1; cvt.u32.u64 %0, t; }" : "=r"(a) : "l"(p));
    return a;
}

__device__ __forceinline__ void cp_async16(uint32_t dst, const void* src) {
    asm volatile("cp.async.cg.shared.global [%0], [%1], 16;" :: "r"(dst), "l"(src));
}
#define CP_COMMIT() asm volatile("cp.async.commit_group;" ::: "memory")
#define CP_WAIT(n)  asm volatile("cp.async.wait_group %0;" :: "n"(n) : "memory")

__device__ __forceinline__ void mma_tf32(float* c, const uint32_t* a, const uint32_t* b) {
    asm volatile(
        "mma.sync.aligned.m16n8k8.row.col.f32.tf32.tf32.f32 "
        "{%0,%1,%2,%3}, {%4,%5,%6,%7}, {%8,%9}, {%0,%1,%2,%3};"
        : "+f"(c[0]), "+f"(c[1]), "+f"(c[2]), "+f"(c[3])
        : "r"(a[0]), "r"(a[1]), "r"(a[2]), "r"(a[3]), "r"(b[0]), "r"(b[1]));
}

#define EPI_NONE 0
#define EPI_SILU 1
#define EPI_SIGM 2
template <int EPI>
__device__ __forceinline__ float epi(float v) {
    if (EPI == EPI_SILU) return v / (1.0f + expf(-v));
    if (EPI == EPI_SIGM) return 1.0f / (1.0f + expf(-v));
    return v;
}

__device__ __forceinline__ float to_tf32(float f) {
    uint32_t u;
    asm("cvt.rna.tf32.f32 %0, %1;" : "=r"(u) : "f"(f));
    return __uint_as_float(u);
}

__global__ __launch_bounds__(256)
void cvt_tf32_kernel(const float* __restrict__ in, float* __restrict__ out, int n4) {
    int i = blockIdx.x * 256 + threadIdx.x;
    if (i < n4) {
        float4 v = ((const float4*)in)[i];
        v.x = to_tf32(v.x); v.y = to_tf32(v.y);
        v.z = to_tf32(v.z); v.w = to_tf32(v.w);
        ((float4*)out)[i] = v;
    }
}

// ---------------- tf32 mma.sync GEMM: C[m][n] = epi(sum_k A[m][k]*B[n][k]) ----------------
// A: M x GK row-major (tf32), B: Ntot x GK row-major (tf32), C: M x Ntot.
// CTA tile 128x256, warp tile 64x64 (2x4 warps), BK=32, 3-stage cp.async.
__device__ __forceinline__ void g_load_stage(uint32_t sbase, int slot, int s,
                                             const float* __restrict__ Ab,
                                             const float* __restrict__ Bb, int t)
{
    const uint32_t stA = sbase + slot * STAGE_BYTES;
    const uint32_t stB = stA + STG_BA;
    const float* ga = Ab + (size_t)s * BK;
    const float* gb = Bb + (size_t)s * BK;
#pragma unroll
    for (int i = 0; i < 4; ++i) {                 // A: 128 rows x 8 float4
        int id = t + 256 * i;
        int row = id >> 3, c = id & 7;
        cp_async16(stA + (row * KPAD + c * 4) * 4, ga + (size_t)row * GK + c * 4);
    }
#pragma unroll
    for (int i = 0; i < 8; ++i) {                 // B: 256 rows x 8 float4
        int id = t + 256 * i;
        int row = id >> 3, c = id & 7;
        cp_async16(stB + (row * KPAD + c * 4) * 4, gb + (size_t)row * GK + c * 4);
    }
}

template <int EPI>
__global__ __launch_bounds__(256, 1)
void gemm_mma(const float* __restrict__ A, const float* __restrict__ B,
              float* __restrict__ C, int Ntot)
{
    extern __shared__ __align__(128) float smem[];
    const uint32_t sbase = smem_u32(smem);
    const int t    = threadIdx.x;
    const int wid  = t >> 5;
    const int lane = t & 31;
    const int bm = blockIdx.y * BM;
    const int bn = blockIdx.x * BN;
    const float* Ab = A + (size_t)bm * GK;
    const float* Bb = B + (size_t)bn * GK;

    const int wm = (wid & 1) * 64;        // warp row offset (0,64)
    const int wn = (wid >> 1) * 64;       // warp col offset (0,64,128,192)
    const int r  = lane >> 2;             // 0..7
    const int kq = lane & 3;              // 0..3

    float c[4][8][4];
#pragma unroll
    for (int i = 0; i < 4; ++i)
#pragma unroll
        for (int j = 0; j < 8; ++j)
#pragma unroll
            for (int q = 0; q < 4; ++q) c[i][j][q] = 0.0f;

    g_load_stage(sbase, 0, 0, Ab, Bb, t); CP_COMMIT();
    g_load_stage(sbase, 1, 1, Ab, Bb, t); CP_COMMIT();

    for (int s = 0; s < KTILES; ++s) {
        const int slot = s % NSTG;
        CP_WAIT(1);
        __syncthreads();

        if (s + 2 < KTILES) {
            g_load_stage(sbase, (s + 2) % NSTG, s + 2, Ab, Bb, t);
        }
        CP_COMMIT();

        const float* As = smem + slot * (STAGE_BYTES / 4);
        const float* Bs = As + STG_FA;

#pragma unroll
        for (int ks = 0; ks < 4; ++ks) {
            const int k0 = ks * 8;
            uint32_t af[4][4], bf[8][2];
#pragma unroll
            for (int i = 0; i < 4; ++i) {
                const float* ap = As + (wm + i * 16 + r) * KPAD + k0 + kq;
                af[i][0] = __float_as_uint(ap[0]);
                af[i][1] = __float_as_uint(ap[8 * KPAD]);
                af[i][2] = __float_as_uint(ap[4]);
                af[i][3] = __float_as_uint(ap[8 * KPAD + 4]);
            }
#pragma unroll
            for (int j = 0; j < 8; ++j) {
                const float* bp = Bs + (wn + j * 8 + r) * KPAD + k0 + kq;
                bf[j][0] = __float_as_uint(bp[0]);
                bf[j][1] = __float_as_uint(bp[4]);
            }
#pragma unroll
            for (int i = 0; i < 4; ++i)
#pragma unroll
                for (int j = 0; j < 8; ++j)
                    mma_tf32(c[i][j], af[i], bf[j]);
        }
    }

    // epilogue
#pragma unroll
    for (int i = 0; i < 4; ++i) {
        const int row0 = bm + wm + i * 16 + r;
#pragma unroll
        for (int j = 0; j < 8; ++j) {
            const int col = bn + wn + j * 8 + 2 * kq;
            float2 v0 = make_float2(epi<EPI>(c[i][j][0]), epi<EPI>(c[i][j][1]));
            float2 v1 = make_float2(epi<EPI>(c[i][j][2]), epi<EPI>(c[i][j][3]));
            *(float2*)(C + (size_t)row0 * Ntot + col)       = v0;
            *(float2*)(C + (size_t)(row0 + 8) * Ntot + col) = v1;
        }
    }
}

// ---------------- attention stage A ----------------
__global__ __launch_bounds__(256)
void attn_kvblocks(const float* __restrict__ slope)
{
    const int b = blockIdx.x;
    const int h = blockIdx.y;
    const float s = slope[h];

    __shared__ float Ks[8][128];
    __shared__ float Vs[8][128];

    const int t  = threadIdx.x;
    const int ty = t >> 4, tx = t & 15;
    const int d0 = ty * 8, e0 = tx * 8;
    const int il = t >> 5;
    const int c4 = (t & 31) * 4;

    const float* kbase = g_qkv + (size_t)(b * BLK) * QKVW + h * 384 + 128;
    const float* vbase = kbase + 128;

    float acc[8][8];
#pragma unroll
    for (int i = 0; i < 8; ++i)
#pragma unroll
        for (int j = 0; j < 8; ++j) acc[i][j] = 0.0f;

    for (int ic = 0; ic < 32; ++ic) {
        const int i = ic * 8 + il;
        const float kd = expf(-s * (float)(255 - i));
        float4 k4 = *(const float4*)(kbase + (size_t)i * QKVW + c4);
        float4 v4 = *(const float4*)(vbase + (size_t)i * QKVW + c4);
        __syncthreads();
        Ks[il][c4 + 0] = k4.x * kd; Ks[il][c4 + 1] = k4.y * kd;
        Ks[il][c4 + 2] = k4.z * kd; Ks[il][c4 + 3] = k4.w * kd;
        *(float4*)&Vs[il][c4] = v4;
        __syncthreads();
#pragma unroll
        for (int ii = 0; ii < 8; ++ii) {
            float4 a0 = *(const float4*)&Ks[ii][d0];
            float4 a1 = *(const float4*)&Ks[ii][d0 + 4];
            float4 b0 = *(const float4*)&Vs[ii][e0];
            float4 b1 = *(const float4*)&Vs[ii][e0 + 4];
            float av[8] = {a0.x, a0.y, a0.z, a0.w, a1.x, a1.y, a1.z, a1.w};
            float bv[8] = {b0.x, b0.y, b0.z, b0.w, b1.x, b1.y, b1.z, b1.w};
#pragma unroll
            for (int i2 = 0; i2 < 8; ++i2)
#pragma unroll
                for (int j = 0; j < 8; ++j) acc[i2][j] += av[i2] * bv[j];
        }
    }

    float* Sp = g_S + (size_t)(h * NB + b) * HD * HD;
#pragma unroll
    for (int i = 0; i < 8; ++i) {
        *(float4*)&Sp[(size_t)(d0 + i) * HD + e0]     = make_float4(acc[i][0], acc[i][1], acc[i][2], acc[i][3]);
        *(float4*)&Sp[(size_t)(d0 + i) * HD + e0 + 4] = make_float4(acc[i][4], acc[i][5], acc[i][6], acc[i][7]);
    }
}

// ---------------- attention stage B ----------------
__global__ void attn_scan(const float* __restrict__ kv_cache, const float* __restrict__ slope)
{
    const int g = blockIdx.x * 256 + threadIdx.x;
    const int h = g >> 14;
    const int e = g & 16383;
    const float dec = expf(-slope[h] * 256.0f);
    float c = kv_cache[(size_t)h * 16384 + e];
    const size_t base = (size_t)h * NB * 16384 + e;
#pragma unroll
    for (int b = 0; b < NB; ++b) {
        g_kvst[base + (size_t)b * 16384] = c;
        c = dec * c + g_S[base + (size_t)b * 16384];
    }
}

// ---------------- attention stage C1 ----------------
__global__ __launch_bounds__(512)
void attn_ointer(const float* __restrict__ slope)
{
    const int b = blockIdx.x;
    const int h = blockIdx.y;
    const float s = slope[h];

    __shared__ float Qs[8][260];
    __shared__ float Ss[8][128];

    const int t  = threadIdx.x;
    const int ty = t >> 4;
    const int tx = t & 15;
    const int m0 = ty * 8, e0 = tx * 8;

    const int lm  = t >> 1;
    const int ld4 = (t & 1) * 4;
    const float qd = expf(-s * (float)(lm + 1));
    const int sd  = t >> 5;
    const int se4 = (t & 31) * 4;

    const float* qbase = g_qkv + (size_t)(b * BLK) * QKVW + h * 384;
    const float* st    = g_kvst + (size_t)(h * NB + b) * HD * HD;

    float acc[8][8];
#pragma unroll
    for (int i = 0; i < 8; ++i)
#pragma unroll
        for (int j = 0; j < 8; ++j) acc[i][j] = 0.0f;

    for (int dc = 0; dc < 16; ++dc) {
        const int d0 = dc * 8;
        float4 q4 = *(const float4*)(qbase + (size_t)lm * QKVW + d0 + ld4);
        float4 s4 = make_float4(0.f, 0.f, 0.f, 0.f);
        if (t < 256) s4 = *(const float4*)(st + (size_t)(d0 + sd) * HD + se4);
        __syncthreads();
        Qs[ld4 + 0][lm] = q4.x * qd; Qs[ld4 + 1][lm] = q4.y * qd;
        Qs[ld4 + 2][lm] = q4.z * qd; Qs[ld4 + 3][lm] = q4.w * qd;
        if (t < 256) *(float4*)&Ss[sd][se4] = s4;
        __syncthreads();
#pragma unroll
        for (int kk = 0; kk < 8; ++kk) {
            float4 a0 = *(const float4*)&Qs[kk][m0];
            float4 a1 = *(const float4*)&Qs[kk][m0 + 4];
            float4 b0 = *(const float4*)&Ss[kk][e0];
            float4 b1 = *(const float4*)&Ss[kk][e0 + 4];
            float av[8] = {a0.x, a0.y, a0.z, a0.w, a1.x, a1.y, a1.z, a1.w};
            float bv[8] = {b0.x, b0.y, b0.z, b0.w, b1.x, b1.y, b1.z, b1.w};
#pragma unroll
            for (int i = 0; i < 8; ++i)
#pragma unroll
                for (int j = 0; j < 8; ++j) acc[i][j] += av[i] * bv[j];
        }
    }

    float* hbase = g_hidden + (size_t)(b * BLK) * INNER + h * HD;
#pragma unroll
    for (int i = 0; i < 8; ++i) {
        float* Hp = hbase + (size_t)(m0 + i) * INNER + e0;
        *(float4*)Hp       = make_float4(acc[i][0], acc[i][1], acc[i][2], acc[i][3]);
        *(float4*)(Hp + 4) = make_float4(acc[i][4], acc[i][5], acc[i][6], acc[i][7]);
    }
}

// ---------------- attention stage C2 ----------------
__global__ __launch_bounds__(256)
void attn_ointra(const float* __restrict__ slope)
{
    const int mt = blockIdx.x;
    const int b  = blockIdx.y;
    const int h  = blockIdx.z;
    const float s = slope[h];

    __shared__ float Qs[32][132];
    __shared__ float KVs[32][132];
    __shared__ float Ps[32][36];

    const int t = threadIdx.x;
    const float* qbase = g_qkv + (size_t)(b * BLK) * QKVW + h * 384;

#pragma unroll
    for (int r = 0; r < 4; ++r) {
        int idx = t + r * 256;
        int mm = idx >> 5, d4 = (idx & 31) * 4;
        float4 q4 = *(const float4*)(qbase + (size_t)(mt * 32 + mm) * QKVW + d4);
        *(float4*)&Qs[mm][d4] = q4;
    }

    const int p_ty = t >> 4, p_tx = t & 15;
    const int pm0  = p_ty * 2;
    const int om0  = p_ty * 2;
    const int e0   = p_tx * 8;

    float oacc[2][8];
#pragma unroll
    for (int i = 0; i < 2; ++i)
#pragma unroll
        for (int j = 0; j < 8; ++j) oacc[i][j] = 0.0f;

    for (int nt = 0; nt <= mt; ++nt) {
        __syncthreads();
#pragma unroll
        for (int r = 0; r < 4; ++r) {
            int idx = t + r * 256;
            int nn = idx >> 5, d4 = (idx & 31) * 4;
            float4 k4 = *(const float4*)(qbase + 128 + (size_t)(nt * 32 + nn) * QKVW + d4);
            *(float4*)&KVs[nn][d4] = k4;
        }
        __syncthreads();

        float p00 = 0.f, p01 = 0.f, p10 = 0.f, p11 = 0.f;
#pragma unroll 4
        for (int d = 0; d < 128; ++d) {
            float a0 = Qs[pm0][d], a1 = Qs[pm0 + 1][d];
            float b0 = KVs[p_tx][d], b1 = KVs[p_tx + 16][d];
            p00 += a0 * b0; p01 += a0 * b1;
            p10 += a1 * b0; p11 += a1 * b1;
        }
        const int mg0 = mt * 32 + pm0, mg1 = mg0 + 1;
        const int ng0 = nt * 32 + p_tx, ng1 = nt * 32 + p_tx + 16;
        Ps[pm0][p_tx]          = (mg0 >= ng0) ? p00 * expf(-s * (float)(mg0 - ng0)) : 0.0f;
        Ps[pm0][p_tx + 16]     = (mg0 >= ng1) ? p01 * expf(-s * (float)(mg0 - ng1)) : 0.0f;
        Ps[pm0 + 1][p_tx]      = (mg1 >= ng0) ? p10 * expf(-s * (float)(mg1 - ng0)) : 0.0f;
        Ps[pm0 + 1][p_tx + 16] = (mg1 >= ng1) ? p11 * expf(-s * (float)(mg1 - ng1)) : 0.0f;
        __syncthreads();

#pragma unroll
        for (int r = 0; r < 4; ++r) {
            int idx = t + r * 256;
            int nn = idx >> 5, d4 = (idx & 31) * 4;
            float4 v4 = *(const float4*)(qbase + 256 + (size_t)(nt * 32 + nn) * QKVW + d4);
            *(float4*)&KVs[nn][d4] = v4;
        }
        __syncthreads();

#pragma unroll 4
        for (int n = 0; n < 32; ++n) {
            float a0 = Ps[om0][n], a1 = Ps[om0 + 1][n];
            float4 v0 = *(const float4*)&KVs[n][e0];
            float4 v1 = *(const float4*)&KVs[n][e0 + 4];
            oacc[0][0] += a0 * v0.x; oacc[0][1] += a0 * v0.y;
            oacc[0][2] += a0 * v0.z; oacc[0][3] += a0 * v0.w;
            oacc[0][4] += a0 * v1.x; oacc[0][5] += a0 * v1.y;
            oacc[0][6] += a0 * v1.z; oacc[0][7] += a0 * v1.w;
            oacc[1][0] += a1 * v0.x; oacc[1][1] += a1 * v0.y;
            oacc[1][2] += a1 * v0.z; oacc[1][3] += a1 * v0.w;
            oacc[1][4] += a1 * v1.x; oacc[1][5] += a1 * v1.y;
            oacc[1][6] += a1 * v1.z; oacc[1][7] += a1 * v1.w;
        }
    }

    float* hbase = g_hidden + (size_t)(b * BLK + mt * 32) * INNER + h * HD;
#pragma unroll
    for (int i = 0; i < 2; ++i) {
        float* Hp = hbase + (size_t)(om0 + i) * INNER + e0;
        float4 o0 = *(float4*)Hp;
        float4 o1 = *(float4*)(Hp + 4);
        o0.x += oacc[i][0]; o0.y += oacc[i][1]; o0.z += oacc[i][2]; o0.w += oacc[i][3];
        o1.x += oacc[i][4]; o1.y += oacc[i][5]; o1.z += oacc[i][6]; o1.w += oacc[i][7];
        *(float4*)Hp       = o0;
        *(float4*)(Hp + 4) = o1;
    }
}

// ---------------- RMSNorm * weight * gate -> tf32-rounded ----------------
__global__ __launch_bounds__(256)
void rmsnorm_gate(const float* __restrict__ nw)
{
    const int m = blockIdx.x;
    const int t = threadIdx.x;
    const float* hrow = g_hidden + (size_t)m * INNER;
    float* grow = g_gate + (size_t)m * INNER;

    float ss = 0.0f;
    for (int i = t; i < INNER / 4; i += 256) {
        float4 h4 = *(const float4*)(hrow + i * 4);
        ss += h4.x * h4.x + h4.y * h4.y + h4.z * h4.z + h4.w * h4.w;
    }
    __shared__ float red[256];
    red[t] = ss;
    __syncthreads();
    for (int s2 = 128; s2 > 0; s2 >>= 1) {
        if (t < s2) red[t] += red[t + s2];
        __syncthreads();
    }
    const float rs = rsqrtf(red[0] / (float)INNER + EPS_RMS);

    for (int i = t; i < INNER / 4; i += 256) {
        float4 h4 = *(const float4*)(hrow + i * 4);
        float4 g4 = *(const float4*)(grow + i * 4);
        float4 w4 = *(const float4*)(nw + i * 4);
        float4 o;
        o.x = to_tf32(g4.x * (h4.x * rs * w4.x));
        o.y = to_tf32(g4.y * (h4.y * rs * w4.y));
        o.z = to_tf32(g4.z * (h4.z * rs * w4.z));
        o.w = to_tf32(g4.w * (h4.w * rs * w4.w));
        *(float4*)(grow + i * 4) = o;
    }
}

// ---------------- launcher ----------------
extern "C" void kernel_launch(void* const* d_in, const int* in_sizes, int n_in,
                              void* d_out, int out_size)
{
    (void)in_sizes; (void)n_in; (void)out_size;
    const float* x     = (const float*)d_in[0];
    const float* wqkv  = (const float*)d_in[1];
    const float* wgate = (const float*)d_in[2];
    const float* wout  = (const float*)d_in[3];
    const float* nw    = (const float*)d_in[4];
    const float* kvc   = (const float*)d_in[5];
    const float* slope = (const float*)d_in[6];
    float* out = (float*)d_out;

    float *p_qkv = nullptr, *p_gate = nullptr, *p_xt = nullptr,
          *p_wqkvt = nullptr, *p_wgatet = nullptr, *p_woutt = nullptr;
    cudaGetSymbolAddress((void**)&p_qkv, g_qkv);
    cudaGetSymbolAddress((void**)&p_gate, g_gate);
    cudaGetSymbolAddress((void**)&p_xt, g_xt);
    cudaGetSymbolAddress((void**)&p_wqkvt, g_wqkvt);
    cudaGetSymbolAddress((void**)&p_wgatet, g_wgatet);
    cudaGetSymbolAddress((void**)&p_woutt, g_woutt);

    cudaFuncSetAttribute(gemm_mma<EPI_SILU>, cudaFuncAttributeMaxDynamicSharedMemorySize, GEMM_SMEM);
    cudaFuncSetAttribute(gemm_mma<EPI_SIGM>, cudaFuncAttributeMaxDynamicSharedMemorySize, GEMM_SMEM);
    cudaFuncSetAttribute(gemm_mma<EPI_NONE>, cudaFuncAttributeMaxDynamicSharedMemorySize, GEMM_SMEM);

    // tf32-round inputs
    cvt_tf32_kernel<<<(SEQ * HDIM / 4 + 255) / 256, 256>>>(x, p_xt, SEQ * HDIM / 4);
    cvt_tf32_kernel<<<(QKVW * HDIM / 4 + 255) / 256, 256>>>(wqkv, p_wqkvt, QKVW * HDIM / 4);
    cvt_tf32_kernel<<<(INNER * HDIM / 4 + 255) / 256, 256>>>(wgate, p_wgatet, INNER * HDIM / 4);
    cvt_tf32_kernel<<<(HDIM * INNER / 4 + 255) / 256, 256>>>(wout, p_woutt, HDIM * INNER / 4);

    // qkv = silu(x @ w_qkv^T)
    gemm_mma<EPI_SILU><<<dim3(QKVW / BN, SEQ / BM), 256, GEMM_SMEM>>>(p_xt, p_wqkvt, p_qkv, QKVW);
    // gate = sigmoid(x @ w_gate^T)
    gemm_mma<EPI_SIGM><<<dim3(INNER / BN, SEQ / BM), 256, GEMM_SMEM>>>(p_xt, p_wgatet, p_gate, INNER);

    // lightning attention (fp32)
    attn_kvblocks<<<dim3(NB, NH), 256>>>(slope);
    attn_scan<<<(NH * HD * HD) / 256, 256>>>(kvc, slope);
    attn_ointer<<<dim3(NB, NH), 512>>>(slope);
    attn_ointra<<<dim3(8, NB, NH), 256>>>(slope);

    // rmsnorm * weight * gate (tf32-rounded output)
    rmsnorm_gate<<<SEQ, 256>>>(nw);

    // out = (gate * normed) @ w_out^T
    gemm_mma<EPI_NONE><<<dim3(HDIM / BN, SEQ / BM), 256, GEMM_SMEM>>>(p_gate, p_woutt, out, HDIM);
}

// round 5
// speedup vs baseline: 3.5426x; 1.0646x over previous
#include <cuda_runtime.h>
#include <math.h>
#include <stdint.h>

#define SEQ   4096
#define HDIM  4096
#define INNER 4096
#define NH    32
#define HD    128
#define BLK   256
#define NB    16
#define QKVW  12288
#define EPS_RMS 1e-5f

#define GK    4096          // shared K dim of all three GEMMs
#define BM    128
#define BN    128
#define BK    32
#define NTHR  128
#define KTILES (GK / BK)    // 128
#define KPAD  36            // 32 + 4 floats pad
#define STG_FA (128 * KPAD)             // A floats per stage (4608)
#define STG_FB (128 * KPAD)             // B floats per stage (4608)
#define STG_BA (STG_FA * 4)             // 18432 bytes
#define STAGE_BYTES ((STG_FA + STG_FB) * 4)   // 36864
#define NSTG  3
#define GEMM_SMEM (NSTG * STAGE_BYTES)  // 110592 -> 2 CTAs/SM

// ---------------- scratch ----------------
__device__ float g_qkv[(size_t)SEQ * QKVW];
__device__ float g_hidden[(size_t)SEQ * INNER];
__device__ float g_gate[(size_t)SEQ * INNER];
__device__ float g_S[(size_t)NH * NB * HD * HD];
__device__ float g_kvst[(size_t)NH * NB * HD * HD];
__device__ float g_xt[(size_t)SEQ * HDIM];
__device__ float g_wqkvt[(size_t)QKVW * HDIM];
__device__ float g_wgatet[(size_t)INNER * HDIM];
__device__ float g_woutt[(size_t)HDIM * INNER];

// ---------------- helpers ----------------
__device__ __forceinline__ uint32_t smem_u32(const void* p) {
    uint32_t a;
    asm("{ .reg .u64 t; cvta.to.shared.u64 t, %1; cvt.u32.u64 %0, t; }" : "=r"(a) : "l"(p));
    return a;
}

__device__ __forceinline__ void cp_async16(uint32_t dst, const void* src) {
    asm volatile("cp.async.cg.shared.global [%0], [%1], 16;" :: "r"(dst), "l"(src));
}
#define CP_COMMIT() asm volatile("cp.async.commit_group;" ::: "memory")
#define CP_WAIT(n)  asm volatile("cp.async.wait_group %0;" :: "n"(n) : "memory")

__device__ __forceinline__ void mma_tf32(float* c, const uint32_t* a, const uint32_t* b) {
    asm volatile(
        "mma.sync.aligned.m16n8k8.row.col.f32.tf32.tf32.f32 "
        "{%0,%1,%2,%3}, {%4,%5,%6,%7}, {%8,%9}, {%0,%1,%2,%3};"
        : "+f"(c[0]), "+f"(c[1]), "+f"(c[2]), "+f"(c[3])
        : "r"(a[0]), "r"(a[1]), "r"(a[2]), "r"(a[3]), "r"(b[0]), "r"(b[1]));
}

#define EPI_NONE 0
#define EPI_SILU 1
#define EPI_SIGM 2
template <int EPI>
__device__ __forceinline__ float epi(float v) {
    if (EPI == EPI_SILU) return v / (1.0f + expf(-v));
    if (EPI == EPI_SIGM) return 1.0f / (1.0f + expf(-v));
    return v;
}

__device__ __forceinline__ float to_tf32(float f) {
    uint32_t u;
    asm("cvt.rna.tf32.f32 %0, %1;" : "=r"(u) : "f"(f));
    return __uint_as_float(u);
}

__global__ __launch_bounds__(256)
void cvt_tf32_kernel(const float* __restrict__ in, float* __restrict__ out, int n4) {
    int i = blockIdx.x * 256 + threadIdx.x;
    if (i < n4) {
        float4 v = ((const float4*)in)[i];
        v.x = to_tf32(v.x); v.y = to_tf32(v.y);
        v.z = to_tf32(v.z); v.w = to_tf32(v.w);
        ((float4*)out)[i] = v;
    }
}

// ---------------- tf32 mma.sync GEMM: C[m][n] = epi(sum_k A[m][k]*B[n][k]) ----------------
// CTA tile 128x128, 128 threads (4 warps, warp tile 64x64), BK=32, 3 stages, 2 CTAs/SM.
__device__ __forceinline__ void g_load_stage(uint32_t sbase, int slot, int s,
                                             const float* __restrict__ Ab,
                                             const float* __restrict__ Bb, int t)
{
    const uint32_t stA = sbase + slot * STAGE_BYTES;
    const uint32_t stB = stA + STG_BA;
    const float* ga = Ab + (size_t)s * BK;
    const float* gb = Bb + (size_t)s * BK;
#pragma unroll
    for (int i = 0; i < 8; ++i) {                 // A: 128 rows x 8 float4
        int id = t + NTHR * i;
        int row = id >> 3, c = id & 7;
        cp_async16(stA + (row * KPAD + c * 4) * 4, ga + (size_t)row * GK + c * 4);
    }
#pragma unroll
    for (int i = 0; i < 8; ++i) {                 // B: 128 rows x 8 float4
        int id = t + NTHR * i;
        int row = id >> 3, c = id & 7;
        cp_async16(stB + (row * KPAD + c * 4) * 4, gb + (size_t)row * GK + c * 4);
    }
}

template <int EPI>
__global__ __launch_bounds__(NTHR, 2)
void gemm_mma(const float* __restrict__ A, const float* __restrict__ B,
              float* __restrict__ C, int Ntot)
{
    extern __shared__ __align__(128) float smem[];
    const uint32_t sbase = smem_u32(smem);
    const int t    = threadIdx.x;
    const int wid  = t >> 5;
    const int lane = t & 31;
    const int bm = blockIdx.y * BM;
    const int bn = blockIdx.x * BN;
    const float* Ab = A + (size_t)bm * GK;
    const float* Bb = B + (size_t)bn * GK;

    const int wm = (wid & 1) * 64;        // warp row offset (0,64)
    const int wn = (wid >> 1) * 64;       // warp col offset (0,64)
    const int r  = lane >> 2;             // 0..7
    const int kq = lane & 3;              // 0..3

    float c[4][8][4];
#pragma unroll
    for (int i = 0; i < 4; ++i)
#pragma unroll
        for (int j = 0; j < 8; ++j)
#pragma unroll
            for (int q = 0; q < 4; ++q) c[i][j][q] = 0.0f;

    g_load_stage(sbase, 0, 0, Ab, Bb, t); CP_COMMIT();
    g_load_stage(sbase, 1, 1, Ab, Bb, t); CP_COMMIT();

    for (int s = 0; s < KTILES; ++s) {
        const int slot = s % NSTG;
        CP_WAIT(1);
        __syncthreads();

        if (s + 2 < KTILES) {
            g_load_stage(sbase, (s + 2) % NSTG, s + 2, Ab, Bb, t);
        }
        CP_COMMIT();

        const float* As = smem + slot * (STAGE_BYTES / 4);
        const float* Bs = As + STG_FA;

#pragma unroll
        for (int ks = 0; ks < 4; ++ks) {
            const int k0 = ks * 8;
            uint32_t af[4][4], bf[8][2];
#pragma unroll
            for (int i = 0; i < 4; ++i) {
                const float* ap = As + (wm + i * 16 + r) * KPAD + k0 + kq;
                af[i][0] = __float_as_uint(ap[0]);
                af[i][1] = __float_as_uint(ap[8 * KPAD]);
                af[i][2] = __float_as_uint(ap[4]);
                af[i][3] = __float_as_uint(ap[8 * KPAD + 4]);
            }
#pragma unroll
            for (int j = 0; j < 8; ++j) {
                const float* bp = Bs + (wn + j * 8 + r) * KPAD + k0 + kq;
                bf[j][0] = __float_as_uint(bp[0]);
                bf[j][1] = __float_as_uint(bp[4]);
            }
#pragma unroll
            for (int i = 0; i < 4; ++i)
#pragma unroll
                for (int j = 0; j < 8; ++j)
                    mma_tf32(c[i][j], af[i], bf[j]);
        }
    }

    // epilogue
#pragma unroll
    for (int i = 0; i < 4; ++i) {
        const int row0 = bm + wm + i * 16 + r;
#pragma unroll
        for (int j = 0; j < 8; ++j) {
            const int col = bn + wn + j * 8 + 2 * kq;
            float2 v0 = make_float2(epi<EPI>(c[i][j][0]), epi<EPI>(c[i][j][1]));
            float2 v1 = make_float2(epi<EPI>(c[i][j][2]), epi<EPI>(c[i][j][3]));
            *(float2*)(C + (size_t)row0 * Ntot + col)       = v0;
            *(float2*)(C + (size_t)(row0 + 8) * Ntot + col) = v1;
        }
    }
}

// ---------------- attention stage A ----------------
__global__ __launch_bounds__(256)
void attn_kvblocks(const float* __restrict__ slope)
{
    const int b = blockIdx.x;
    const int h = blockIdx.y;
    const float s = slope[h];

    __shared__ float Ks[8][128];
    __shared__ float Vs[8][128];

    const int t  = threadIdx.x;
    const int ty = t >> 4, tx = t & 15;
    const int d0 = ty * 8, e0 = tx * 8;
    const int il = t >> 5;
    const int c4 = (t & 31) * 4;

    const float* kbase = g_qkv + (size_t)(b * BLK) * QKVW + h * 384 + 128;
    const float* vbase = kbase + 128;

    float acc[8][8];
#pragma unroll
    for (int i = 0; i < 8; ++i)
#pragma unroll
        for (int j = 0; j < 8; ++j) acc[i][j] = 0.0f;

    for (int ic = 0; ic < 32; ++ic) {
        const int i = ic * 8 + il;
        const float kd = expf(-s * (float)(255 - i));
        float4 k4 = *(const float4*)(kbase + (size_t)i * QKVW + c4);
        float4 v4 = *(const float4*)(vbase + (size_t)i * QKVW + c4);
        __syncthreads();
        Ks[il][c4 + 0] = k4.x * kd; Ks[il][c4 + 1] = k4.y * kd;
        Ks[il][c4 + 2] = k4.z * kd; Ks[il][c4 + 3] = k4.w * kd;
        *(float4*)&Vs[il][c4] = v4;
        __syncthreads();
#pragma unroll
        for (int ii = 0; ii < 8; ++ii) {
            float4 a0 = *(const float4*)&Ks[ii][d0];
            float4 a1 = *(const float4*)&Ks[ii][d0 + 4];
            float4 b0 = *(const float4*)&Vs[ii][e0];
            float4 b1 = *(const float4*)&Vs[ii][e0 + 4];
            float av[8] = {a0.x, a0.y, a0.z, a0.w, a1.x, a1.y, a1.z, a1.w};
            float bv[8] = {b0.x, b0.y, b0.z, b0.w, b1.x, b1.y, b1.z, b1.w};
#pragma unroll
            for (int i2 = 0; i2 < 8; ++i2)
#pragma unroll
                for (int j = 0; j < 8; ++j) acc[i2][j] += av[i2] * bv[j];
        }
    }

    float* Sp = g_S + (size_t)(h * NB + b) * HD * HD;
#pragma unroll
    for (int i = 0; i < 8; ++i) {
        *(float4*)&Sp[(size_t)(d0 + i) * HD + e0]     = make_float4(acc[i][0], acc[i][1], acc[i][2], acc[i][3]);
        *(float4*)&Sp[(size_t)(d0 + i) * HD + e0 + 4] = make_float4(acc[i][4], acc[i][5], acc[i][6], acc[i][7]);
    }
}

// ---------------- attention stage B ----------------
__global__ void attn_scan(const float* __restrict__ kv_cache, const float* __restrict__ slope)
{
    const int g = blockIdx.x * 256 + threadIdx.x;
    const int h = g >> 14;
    const int e = g & 16383;
    const float dec = expf(-slope[h] * 256.0f);
    float c = kv_cache[(size_t)h * 16384 + e];
    const size_t base = (size_t)h * NB * 16384 + e;
#pragma unroll
    for (int b = 0; b < NB; ++b) {
        g_kvst[base + (size_t)b * 16384] = c;
        c = dec * c + g_S[base + (size_t)b * 16384];
    }
}

// ---------------- attention stage C1 ----------------
__global__ __launch_bounds__(512)
void attn_ointer(const float* __restrict__ slope)
{
    const int b = blockIdx.x;
    const int h = blockIdx.y;
    const float s = slope[h];

    __shared__ float Qs[8][260];
    __shared__ float Ss[8][128];

    const int t  = threadIdx.x;
    const int ty = t >> 4;
    const int tx = t & 15;
    const int m0 = ty * 8, e0 = tx * 8;

    const int lm  = t >> 1;
    const int ld4 = (t & 1) * 4;
    const float qd = expf(-s * (float)(lm + 1));
    const int sd  = t >> 5;
    const int se4 = (t & 31) * 4;

    const float* qbase = g_qkv + (size_t)(b * BLK) * QKVW + h * 384;
    const float* st    = g_kvst + (size_t)(h * NB + b) * HD * HD;

    float acc[8][8];
#pragma unroll
    for (int i = 0; i < 8; ++i)
#pragma unroll
        for (int j = 0; j < 8; ++j) acc[i][j] = 0.0f;

    for (int dc = 0; dc < 16; ++dc) {
        const int d0 = dc * 8;
        float4 q4 = *(const float4*)(qbase + (size_t)lm * QKVW + d0 + ld4);
        float4 s4 = make_float4(0.f, 0.f, 0.f, 0.f);
        if (t < 256) s4 = *(const float4*)(st + (size_t)(d0 + sd) * HD + se4);
        __syncthreads();
        Qs[ld4 + 0][lm] = q4.x * qd; Qs[ld4 + 1][lm] = q4.y * qd;
        Qs[ld4 + 2][lm] = q4.z * qd; Qs[ld4 + 3][lm] = q4.w * qd;
        if (t < 256) *(float4*)&Ss[sd][se4] = s4;
        __syncthreads();
#pragma unroll
        for (int kk = 0; kk < 8; ++kk) {
            float4 a0 = *(const float4*)&Qs[kk][m0];
            float4 a1 = *(const float4*)&Qs[kk][m0 + 4];
            float4 b0 = *(const float4*)&Ss[kk][e0];
            float4 b1 = *(const float4*)&Ss[kk][e0 + 4];
            float av[8] = {a0.x, a0.y, a0.z, a0.w, a1.x, a1.y, a1.z, a1.w};
            float bv[8] = {b0.x, b0.y, b0.z, b0.w, b1.x, b1.y, b1.z, b1.w};
#pragma unroll
            for (int i = 0; i < 8; ++i)
#pragma unroll
                for (int j = 0; j < 8; ++j) acc[i][j] += av[i] * bv[j];
        }
    }

    float* hbase = g_hidden + (size_t)(b * BLK) * INNER + h * HD;
#pragma unroll
    for (int i = 0; i < 8; ++i) {
        float* Hp = hbase + (size_t)(m0 + i) * INNER + e0;
        *(float4*)Hp       = make_float4(acc[i][0], acc[i][1], acc[i][2], acc[i][3]);
        *(float4*)(Hp + 4) = make_float4(acc[i][4], acc[i][5], acc[i][6], acc[i][7]);
    }
}

// ---------------- attention stage C2 ----------------
__global__ __launch_bounds__(256)
void attn_ointra(const float* __restrict__ slope)
{
    const int mt = blockIdx.x;
    const int b  = blockIdx.y;
    const int h  = blockIdx.z;
    const float s = slope[h];

    __shared__ float Qs[32][132];
    __shared__ float KVs[32][132];
    __shared__ float Ps[32][36];

    const int t = threadIdx.x;
    const float* qbase = g_qkv + (size_t)(b * BLK) * QKVW + h * 384;

#pragma unroll
    for (int r = 0; r < 4; ++r) {
        int idx = t + r * 256;
        int mm = idx >> 5, d4 = (idx & 31) * 4;
        float4 q4 = *(const float4*)(qbase + (size_t)(mt * 32 + mm) * QKVW + d4);
        *(float4*)&Qs[mm][d4] = q4;
    }

    const int p_ty = t >> 4, p_tx = t & 15;
    const int pm0  = p_ty * 2;
    const int om0  = p_ty * 2;
    const int e0   = p_tx * 8;

    float oacc[2][8];
#pragma unroll
    for (int i = 0; i < 2; ++i)
#pragma unroll
        for (int j = 0; j < 8; ++j) oacc[i][j] = 0.0f;

    for (int nt = 0; nt <= mt; ++nt) {
        __syncthreads();
#pragma unroll
        for (int r = 0; r < 4; ++r) {
            int idx = t + r * 256;
            int nn = idx >> 5, d4 = (idx & 31) * 4;
            float4 k4 = *(const float4*)(qbase + 128 + (size_t)(nt * 32 + nn) * QKVW + d4);
            *(float4*)&KVs[nn][d4] = k4;
        }
        __syncthreads();

        float p00 = 0.f, p01 = 0.f, p10 = 0.f, p11 = 0.f;
#pragma unroll 4
        for (int d = 0; d < 128; ++d) {
            float a0 = Qs[pm0][d], a1 = Qs[pm0 + 1][d];
            float b0 = KVs[p_tx][d], b1 = KVs[p_tx + 16][d];
            p00 += a0 * b0; p01 += a0 * b1;
            p10 += a1 * b0; p11 += a1 * b1;
        }
        const int mg0 = mt * 32 + pm0, mg1 = mg0 + 1;
        const int ng0 = nt * 32 + p_tx, ng1 = nt * 32 + p_tx + 16;
        Ps[pm0][p_tx]          = (mg0 >= ng0) ? p00 * expf(-s * (float)(mg0 - ng0)) : 0.0f;
        Ps[pm0][p_tx + 16]     = (mg0 >= ng1) ? p01 * expf(-s * (float)(mg0 - ng1)) : 0.0f;
        Ps[pm0 + 1][p_tx]      = (mg1 >= ng0) ? p10 * expf(-s * (float)(mg1 - ng0)) : 0.0f;
        Ps[pm0 + 1][p_tx + 16] = (mg1 >= ng1) ? p11 * expf(-s * (float)(mg1 - ng1)) : 0.0f;
        __syncthreads();

#pragma unroll
        for (int r = 0; r < 4; ++r) {
            int idx = t + r * 256;
            int nn = idx >> 5, d4 = (idx & 31) * 4;
            float4 v4 = *(const float4*)(qbase + 256 + (size_t)(nt * 32 + nn) * QKVW + d4);
            *(float4*)&KVs[nn][d4] = v4;
        }
        __syncthreads();

#pragma unroll 4
        for (int n = 0; n < 32; ++n) {
            float a0 = Ps[om0][n], a1 = Ps[om0 + 1][n];
            float4 v0 = *(const float4*)&KVs[n][e0];
            float4 v1 = *(const float4*)&KVs[n][e0 + 4];
            oacc[0][0] += a0 * v0.x; oacc[0][1] += a0 * v0.y;
            oacc[0][2] += a0 * v0.z; oacc[0][3] += a0 * v0.w;
            oacc[0][4] += a0 * v1.x; oacc[0][5] += a0 * v1.y;
            oacc[0][6] += a0 * v1.z; oacc[0][7] += a0 * v1.w;
            oacc[1][0] += a1 * v0.x; oacc[1][1] += a1 * v0.y;
            oacc[1][2] += a1 * v0.z; oacc[1][3] += a1 * v0.w;
            oacc[1][4] += a1 * v1.x; oacc[1][5] += a1 * v1.y;
            oacc[1][6] += a1 * v1.z; oacc[1][7] += a1 * v1.w;
        }
    }

    float* hbase = g_hidden + (size_t)(b * BLK + mt * 32) * INNER + h * HD;
#pragma unroll
    for (int i = 0; i < 2; ++i) {
        float* Hp = hbase + (size_t)(om0 + i) * INNER + e0;
        float4 o0 = *(float4*)Hp;
        float4 o1 = *(float4*)(Hp + 4);
        o0.x += oacc[i][0]; o0.y += oacc[i][1]; o0.z += oacc[i][2]; o0.w += oacc[i][3];
        o1.x += oacc[i][4]; o1.y += oacc[i][5]; o1.z += oacc[i][6]; o1.w += oacc[i][7];
        *(float4*)Hp       = o0;
        *(float4*)(Hp + 4) = o1;
    }
}

// ---------------- RMSNorm * weight * gate -> tf32-rounded ----------------
__global__ __launch_bounds__(256)
void rmsnorm_gate(const float* __restrict__ nw)
{
    const int m = blockIdx.x;
    const int t = threadIdx.x;
    const float* hrow = g_hidden + (size_t)m * INNER;
    float* grow = g_gate + (size_t)m * INNER;

    float ss = 0.0f;
    for (int i = t; i < INNER / 4; i += 256) {
        float4 h4 = *(const float4*)(hrow + i * 4);
        ss += h4.x * h4.x + h4.y * h4.y + h4.z * h4.z + h4.w * h4.w;
    }
    __shared__ float red[256];
    red[t] = ss;
    __syncthreads();
    for (int s2 = 128; s2 > 0; s2 >>= 1) {
        if (t < s2) red[t] += red[t + s2];
        __syncthreads();
    }
    const float rs = rsqrtf(red[0] / (float)INNER + EPS_RMS);

    for (int i = t; i < INNER / 4; i += 256) {
        float4 h4 = *(const float4*)(hrow + i * 4);
        float4 g4 = *(const float4*)(grow + i * 4);
        float4 w4 = *(const float4*)(nw + i * 4);
        float4 o;
        o.x = to_tf32(g4.x * (h4.x * rs * w4.x));
        o.y = to_tf32(g4.y * (h4.y * rs * w4.y));
        o.z = to_tf32(g4.z * (h4.z * rs * w4.z));
        o.w = to_tf32(g4.w * (h4.w * rs * w4.w));
        *(float4*)(grow + i * 4) = o;
    }
}

// ---------------- launcher ----------------
extern "C" void kernel_launch(void* const* d_in, const int* in_sizes, int n_in,
                              void* d_out, int out_size)
{
    (void)in_sizes; (void)n_in; (void)out_size;
    const float* x     = (const float*)d_in[0];
    const float* wqkv  = (const float*)d_in[1];
    const float* wgate = (const float*)d_in[2];
    const float* wout  = (const float*)d_in[3];
    const float* nw    = (const float*)d_in[4];
    const float* kvc   = (const float*)d_in[5];
    const float* slope = (const float*)d_in[6];
    float* out = (float*)d_out;

    float *p_qkv = nullptr, *p_gate = nullptr, *p_xt = nullptr,
          *p_wqkvt = nullptr, *p_wgatet = nullptr, *p_woutt = nullptr;
    cudaGetSymbolAddress((void**)&p_qkv, g_qkv);
    cudaGetSymbolAddress((void**)&p_gate, g_gate);
    cudaGetSymbolAddress((void**)&p_xt, g_xt);
    cudaGetSymbolAddress((void**)&p_wqkvt, g_wqkvt);
    cudaGetSymbolAddress((void**)&p_wgatet, g_wgatet);
    cudaGetSymbolAddress((void**)&p_woutt, g_woutt);

    cudaFuncSetAttribute(gemm_mma<EPI_SILU>, cudaFuncAttributeMaxDynamicSharedMemorySize, GEMM_SMEM);
    cudaFuncSetAttribute(gemm_mma<EPI_SIGM>, cudaFuncAttributeMaxDynamicSharedMemorySize, GEMM_SMEM);
    cudaFuncSetAttribute(gemm_mma<EPI_NONE>, cudaFuncAttributeMaxDynamicSharedMemorySize, GEMM_SMEM);

    // tf32-round inputs
    cvt_tf32_kernel<<<(SEQ * HDIM / 4 + 255) / 256, 256>>>(x, p_xt, SEQ * HDIM / 4);
    cvt_tf32_kernel<<<(QKVW * HDIM / 4 + 255) / 256, 256>>>(wqkv, p_wqkvt, QKVW * HDIM / 4);
    cvt_tf32_kernel<<<(INNER * HDIM / 4 + 255) / 256, 256>>>(wgate, p_wgatet, INNER * HDIM / 4);
    cvt_tf32_kernel<<<(HDIM * INNER / 4 + 255) / 256, 256>>>(wout, p_woutt, HDIM * INNER / 4);

    // qkv = silu(x @ w_qkv^T)
    gemm_mma<EPI_SILU><<<dim3(QKVW / BN, SEQ / BM), NTHR, GEMM_SMEM>>>(p_xt, p_wqkvt, p_qkv, QKVW);
    // gate = sigmoid(x @ w_gate^T)
    gemm_mma<EPI_SIGM><<<dim3(INNER / BN, SEQ / BM), NTHR, GEMM_SMEM>>>(p_xt, p_wgatet, p_gate, INNER);

    // lightning attention (fp32)
    attn_kvblocks<<<dim3(NB, NH), 256>>>(slope);
    attn_scan<<<(NH * HD * HD) / 256, 256>>>(kvc, slope);
    attn_ointer<<<dim3(NB, NH), 512>>>(slope);
    attn_ointra<<<dim3(8, NB, NH), 256>>>(slope);

    // rmsnorm * weight * gate (tf32-rounded output)
    rmsnorm_gate<<<SEQ, 256>>>(nw);

    // out = (gate * normed) @ w_out^T
    gemm_mma<EPI_NONE><<<dim3(HDIM / BN, SEQ / BM), NTHR, GEMM_SMEM>>>(p_gate, p_woutt, out, HDIM);
}

// round 6
// speedup vs baseline: 5.8815x; 1.6602x over previous
#include <cuda_runtime.h>
#include <cuda_fp16.h>
#include <math.h>
#include <stdint.h>

#define SEQ   4096
#define HDIM  4096
#define INNER 4096
#define NH    32
#define HD    128
#define BLK   256
#define NB    16
#define QKVW  12288
#define EPS_RMS 1e-5f

#define GK    4096          // shared K dim of all three GEMMs
#define BM    128
#define BN    128
#define BK    64
#define NTHR  128
#define KTILES (GK / BK)    // 64
#define KPADH 72            // 64 + 8 halfs pad (144B row stride, conflict-free)
#define STGH_A (128 * KPADH)            // halfs per operand per stage (9216)
#define STAGE_BYTES (2 * STGH_A * 2)    // A + B bytes = 36864
#define NSTG  3
#define GEMM_SMEM (NSTG * STAGE_BYTES)  // 110592 -> 2 CTAs/SM

// ---------------- scratch ----------------
__device__ float  g_qkv[(size_t)SEQ * QKVW];      // fp32 silu(x@w_qkv^T) for attention
__device__ float  g_hidden[(size_t)SEQ * INNER];  // attention output
__device__ float  g_gate[(size_t)SEQ * INNER];    // sigmoid(x@w_gate^T)
__device__ float  g_S[(size_t)NH * NB * HD * HD];
__device__ float  g_kvst[(size_t)NH * NB * HD * HD];
__device__ __half g_xh[(size_t)SEQ * HDIM];       // fp16 inputs for GEMMs
__device__ __half g_wqkvh[(size_t)QKVW * HDIM];
__device__ __half g_wgateh[(size_t)INNER * HDIM];
__device__ __half g_wouth[(size_t)HDIM * INNER];
__device__ __half g_ghalf[(size_t)SEQ * INNER];   // fp16 (gate*normed) for GEMM3

// ---------------- helpers ----------------
__device__ __forceinline__ uint32_t smem_u32(const void* p) {
    uint32_t a;
    asm("{ .reg .u64 t; cvta.to.shared.u64 t, %1; cvt.u32.u64 %0, t; }" : "=r"(a) : "l"(p));
    return a;
}

__device__ __forceinline__ void cp_async16(uint32_t dst, const void* src) {
    asm volatile("cp.async.cg.shared.global [%0], [%1], 16;" :: "r"(dst), "l"(src));
}
#define CP_COMMIT() asm volatile("cp.async.commit_group;" ::: "memory")
#define CP_WAIT(n)  asm volatile("cp.async.wait_group %0;" :: "n"(n) : "memory")

__device__ __forceinline__ void mma_f16(float* c, const uint32_t* a, const uint32_t* b) {
    asm volatile(
        "mma.sync.aligned.m16n8k16.row.col.f32.f16.f16.f32 "
        "{%0,%1,%2,%3}, {%4,%5,%6,%7}, {%8,%9}, {%0,%1,%2,%3};"
        : "+f"(c[0]), "+f"(c[1]), "+f"(c[2]), "+f"(c[3])
        : "r"(a[0]), "r"(a[1]), "r"(a[2]), "r"(a[3]), "r"(b[0]), "r"(b[1]));
}

#define EPI_NONE 0
#define EPI_SILU 1
#define EPI_SIGM 2
template <int EPI>
__device__ __forceinline__ float epi(float v) {
    if (EPI == EPI_SILU) return v / (1.0f + expf(-v));
    if (EPI == EPI_SIGM) return 1.0f / (1.0f + expf(-v));
    return v;
}

// fp32 -> fp16 conversion kernel: each thread converts 8 floats -> 16B store
__global__ __launch_bounds__(256)
void cvt_f16_kernel(const float* __restrict__ in, __half* __restrict__ out, int n8) {
    int i = blockIdx.x * 256 + threadIdx.x;
    if (i < n8) {
        float4 v0 = ((const float4*)in)[i * 2];
        float4 v1 = ((const float4*)in)[i * 2 + 1];
        __half2 h0 = __floats2half2_rn(v0.x, v0.y);
        __half2 h1 = __floats2half2_rn(v0.z, v0.w);
        __half2 h2 = __floats2half2_rn(v1.x, v1.y);
        __half2 h3 = __floats2half2_rn(v1.z, v1.w);
        uint4 o;
        o.x = *(uint32_t*)&h0; o.y = *(uint32_t*)&h1;
        o.z = *(uint32_t*)&h2; o.w = *(uint32_t*)&h3;
        ((uint4*)out)[i] = o;
    }
}

// ---------------- fp16 mma.sync GEMM: C[m][n] = epi(sum_k A[m][k]*B[n][k]) ----------------
// CTA tile 128x128, 128 threads (4 warps, warp tile 64x64), BK=64, 3 stages, 2 CTAs/SM.
__device__ __forceinline__ void g_load_stage(uint32_t sbase, int slot, int s,
                                             const __half* __restrict__ Ab,
                                             const __half* __restrict__ Bb, int t)
{
    const uint32_t stA = sbase + slot * STAGE_BYTES;
    const uint32_t stB = stA + STGH_A * 2;
    const __half* ga = Ab + (size_t)s * BK;
    const __half* gb = Bb + (size_t)s * BK;
#pragma unroll
    for (int i = 0; i < 8; ++i) {                 // A: 128 rows x 8 chunks of 8 halfs
        int id = t + NTHR * i;
        int row = id >> 3, c = id & 7;
        cp_async16(stA + (row * KPADH + c * 8) * 2, ga + (size_t)row * GK + c * 8);
    }
#pragma unroll
    for (int i = 0; i < 8; ++i) {                 // B: 128 rows x 8 chunks
        int id = t + NTHR * i;
        int row = id >> 3, c = id & 7;
        cp_async16(stB + (row * KPADH + c * 8) * 2, gb + (size_t)row * GK + c * 8);
    }
}

template <int EPI>
__global__ __launch_bounds__(NTHR, 2)
void gemm_mma(const __half* __restrict__ A, const __half* __restrict__ B,
              float* __restrict__ C, int Ntot)
{
    extern __shared__ __align__(128) __half smem[];
    const uint32_t sbase = smem_u32(smem);
    const int t    = threadIdx.x;
    const int wid  = t >> 5;
    const int lane = t & 31;
    const int bm = blockIdx.y * BM;
    const int bn = blockIdx.x * BN;
    const __half* Ab = A + (size_t)bm * GK;
    const __half* Bb = B + (size_t)bn * GK;

    const int wm = (wid & 1) * 64;        // warp row offset (0,64)
    const int wn = (wid >> 1) * 64;       // warp col offset (0,64)
    const int r  = lane >> 2;             // 0..7
    const int q  = lane & 3;              // 0..3

    float c[4][8][4];
#pragma unroll
    for (int i = 0; i < 4; ++i)
#pragma unroll
        for (int j = 0; j < 8; ++j)
#pragma unroll
            for (int p = 0; p < 4; ++p) c[i][j][p] = 0.0f;

    g_load_stage(sbase, 0, 0, Ab, Bb, t); CP_COMMIT();
    g_load_stage(sbase, 1, 1, Ab, Bb, t); CP_COMMIT();

    for (int s = 0; s < KTILES; ++s) {
        const int slot = s % NSTG;
        CP_WAIT(1);
        __syncthreads();

        if (s + 2 < KTILES) {
            g_load_stage(sbase, (s + 2) % NSTG, s + 2, Ab, Bb, t);
        }
        CP_COMMIT();

        const __half* As = smem + slot * (STAGE_BYTES / 2);
        const __half* Bs = As + STGH_A;

#pragma unroll
        for (int ks = 0; ks < 4; ++ks) {          // 4 k16 slices per BK=64
            const int k0 = ks * 16;
            uint32_t af[4][4], bf[8][2];
#pragma unroll
            for (int i = 0; i < 4; ++i) {
                const __half* ap = As + (wm + i * 16 + r) * KPADH + k0 + 2 * q;
                af[i][0] = *(const uint32_t*)(ap);
                af[i][1] = *(const uint32_t*)(ap + 8 * KPADH);
                af[i][2] = *(const uint32_t*)(ap + 8);
                af[i][3] = *(const uint32_t*)(ap + 8 * KPADH + 8);
            }
#pragma unroll
            for (int j = 0; j < 8; ++j) {
                const __half* bp = Bs + (wn + j * 8 + r) * KPADH + k0 + 2 * q;
                bf[j][0] = *(const uint32_t*)(bp);
                bf[j][1] = *(const uint32_t*)(bp + 8);
            }
#pragma unroll
            for (int i = 0; i < 4; ++i)
#pragma unroll
                for (int j = 0; j < 8; ++j)
                    mma_f16(c[i][j], af[i], bf[j]);
        }
    }

    // epilogue (c0,c1 -> row r; c2,c3 -> row r+8; cols 2q,2q+1)
#pragma unroll
    for (int i = 0; i < 4; ++i) {
        const int row0 = bm + wm + i * 16 + r;
#pragma unroll
        for (int j = 0; j < 8; ++j) {
            const int col = bn + wn + j * 8 + 2 * q;
            float2 v0 = make_float2(epi<EPI>(c[i][j][0]), epi<EPI>(c[i][j][1]));
            float2 v1 = make_float2(epi<EPI>(c[i][j][2]), epi<EPI>(c[i][j][3]));
            *(float2*)(C + (size_t)row0 * Ntot + col)       = v0;
            *(float2*)(C + (size_t)(row0 + 8) * Ntot + col) = v1;
        }
    }
}

// ---------------- attention stage A ----------------
__global__ __launch_bounds__(256)
void attn_kvblocks(const float* __restrict__ slope)
{
    const int b = blockIdx.x;
    const int h = blockIdx.y;
    const float s = slope[h];

    __shared__ float Ks[8][128];
    __shared__ float Vs[8][128];

    const int t  = threadIdx.x;
    const int ty = t >> 4, tx = t & 15;
    const int d0 = ty * 8, e0 = tx * 8;
    const int il = t >> 5;
    const int c4 = (t & 31) * 4;

    const float* kbase = g_qkv + (size_t)(b * BLK) * QKVW + h * 384 + 128;
    const float* vbase = kbase + 128;

    float acc[8][8];
#pragma unroll
    for (int i = 0; i < 8; ++i)
#pragma unroll
        for (int j = 0; j < 8; ++j) acc[i][j] = 0.0f;

    for (int ic = 0; ic < 32; ++ic) {
        const int i = ic * 8 + il;
        const float kd = expf(-s * (float)(255 - i));
        float4 k4 = *(const float4*)(kbase + (size_t)i * QKVW + c4);
        float4 v4 = *(const float4*)(vbase + (size_t)i * QKVW + c4);
        __syncthreads();
        Ks[il][c4 + 0] = k4.x * kd; Ks[il][c4 + 1] = k4.y * kd;
        Ks[il][c4 + 2] = k4.z * kd; Ks[il][c4 + 3] = k4.w * kd;
        *(float4*)&Vs[il][c4] = v4;
        __syncthreads();
#pragma unroll
        for (int ii = 0; ii < 8; ++ii) {
            float4 a0 = *(const float4*)&Ks[ii][d0];
            float4 a1 = *(const float4*)&Ks[ii][d0 + 4];
            float4 b0 = *(const float4*)&Vs[ii][e0];
            float4 b1 = *(const float4*)&Vs[ii][e0 + 4];
            float av[8] = {a0.x, a0.y, a0.z, a0.w, a1.x, a1.y, a1.z, a1.w};
            float bv[8] = {b0.x, b0.y, b0.z, b0.w, b1.x, b1.y, b1.z, b1.w};
#pragma unroll
            for (int i2 = 0; i2 < 8; ++i2)
#pragma unroll
                for (int j = 0; j < 8; ++j) acc[i2][j] += av[i2] * bv[j];
        }
    }

    float* Sp = g_S + (size_t)(h * NB + b) * HD * HD;
#pragma unroll
    for (int i = 0; i < 8; ++i) {
        *(float4*)&Sp[(size_t)(d0 + i) * HD + e0]     = make_float4(acc[i][0], acc[i][1], acc[i][2], acc[i][3]);
        *(float4*)&Sp[(size_t)(d0 + i) * HD + e0 + 4] = make_float4(acc[i][4], acc[i][5], acc[i][6], acc[i][7]);
    }
}

// ---------------- attention stage B ----------------
__global__ void attn_scan(const float* __restrict__ kv_cache, const float* __restrict__ slope)
{
    const int g = blockIdx.x * 256 + threadIdx.x;
    const int h = g >> 14;
    const int e = g & 16383;
    const float dec = expf(-slope[h] * 256.0f);
    float c = kv_cache[(size_t)h * 16384 + e];
    const size_t base = (size_t)h * NB * 16384 + e;
#pragma unroll
    for (int b = 0; b < NB; ++b) {
        g_kvst[base + (size_t)b * 16384] = c;
        c = dec * c + g_S[base + (size_t)b * 16384];
    }
}

// ---------------- attention stage C1 ----------------
__global__ __launch_bounds__(512)
void attn_ointer(const float* __restrict__ slope)
{
    const int b = blockIdx.x;
    const int h = blockIdx.y;
    const float s = slope[h];

    __shared__ float Qs[8][260];
    __shared__ float Ss[8][128];

    const int t  = threadIdx.x;
    const int ty = t >> 4;
    const int tx = t & 15;
    const int m0 = ty * 8, e0 = tx * 8;

    const int lm  = t >> 1;
    const int ld4 = (t & 1) * 4;
    const float qd = expf(-s * (float)(lm + 1));
    const int sd  = t >> 5;
    const int se4 = (t & 31) * 4;

    const float* qbase = g_qkv + (size_t)(b * BLK) * QKVW + h * 384;
    const float* st    = g_kvst + (size_t)(h * NB + b) * HD * HD;

    float acc[8][8];
#pragma unroll
    for (int i = 0; i < 8; ++i)
#pragma unroll
        for (int j = 0; j < 8; ++j) acc[i][j] = 0.0f;

    for (int dc = 0; dc < 16; ++dc) {
        const int d0 = dc * 8;
        float4 q4 = *(const float4*)(qbase + (size_t)lm * QKVW + d0 + ld4);
        float4 s4 = make_float4(0.f, 0.f, 0.f, 0.f);
        if (t < 256) s4 = *(const float4*)(st + (size_t)(d0 + sd) * HD + se4);
        __syncthreads();
        Qs[ld4 + 0][lm] = q4.x * qd; Qs[ld4 + 1][lm] = q4.y * qd;
        Qs[ld4 + 2][lm] = q4.z * qd; Qs[ld4 + 3][lm] = q4.w * qd;
        if (t < 256) *(float4*)&Ss[sd][se4] = s4;
        __syncthreads();
#pragma unroll
        for (int kk = 0; kk < 8; ++kk) {
            float4 a0 = *(const float4*)&Qs[kk][m0];
            float4 a1 = *(const float4*)&Qs[kk][m0 + 4];
            float4 b0 = *(const float4*)&Ss[kk][e0];
            float4 b1 = *(const float4*)&Ss[kk][e0 + 4];
            float av[8] = {a0.x, a0.y, a0.z, a0.w, a1.x, a1.y, a1.z, a1.w};
            float bv[8] = {b0.x, b0.y, b0.z, b0.w, b1.x, b1.y, b1.z, b1.w};
#pragma unroll
            for (int i = 0; i < 8; ++i)
#pragma unroll
                for (int j = 0; j < 8; ++j) acc[i][j] += av[i] * bv[j];
        }
    }

    float* hbase = g_hidden + (size_t)(b * BLK) * INNER + h * HD;
#pragma unroll
    for (int i = 0; i < 8; ++i) {
        float* Hp = hbase + (size_t)(m0 + i) * INNER + e0;
        *(float4*)Hp       = make_float4(acc[i][0], acc[i][1], acc[i][2], acc[i][3]);
        *(float4*)(Hp + 4) = make_float4(acc[i][4], acc[i][5], acc[i][6], acc[i][7]);
    }
}

// ---------------- attention stage C2 ----------------
__global__ __launch_bounds__(256)
void attn_ointra(const float* __restrict__ slope)
{
    const int mt = blockIdx.x;
    const int b  = blockIdx.y;
    const int h  = blockIdx.z;
    const float s = slope[h];

    __shared__ float Qs[32][132];
    __shared__ float KVs[32][132];
    __shared__ float Ps[32][36];

    const int t = threadIdx.x;
    const float* qbase = g_qkv + (size_t)(b * BLK) * QKVW + h * 384;

#pragma unroll
    for (int r = 0; r < 4; ++r) {
        int idx = t + r * 256;
        int mm = idx >> 5, d4 = (idx & 31) * 4;
        float4 q4 = *(const float4*)(qbase + (size_t)(mt * 32 + mm) * QKVW + d4);
        *(float4*)&Qs[mm][d4] = q4;
    }

    const int p_ty = t >> 4, p_tx = t & 15;
    const int pm0  = p_ty * 2;
    const int om0  = p_ty * 2;
    const int e0   = p_tx * 8;

    float oacc[2][8];
#pragma unroll
    for (int i = 0; i < 2; ++i)
#pragma unroll
        for (int j = 0; j < 8; ++j) oacc[i][j] = 0.0f;

    for (int nt = 0; nt <= mt; ++nt) {
        __syncthreads();
#pragma unroll
        for (int r = 0; r < 4; ++r) {
            int idx = t + r * 256;
            int nn = idx >> 5, d4 = (idx & 31) * 4;
            float4 k4 = *(const float4*)(qbase + 128 + (size_t)(nt * 32 + nn) * QKVW + d4);
            *(float4*)&KVs[nn][d4] = k4;
        }
        __syncthreads();

        float p00 = 0.f, p01 = 0.f, p10 = 0.f, p11 = 0.f;
#pragma unroll 4
        for (int d = 0; d < 128; ++d) {
            float a0 = Qs[pm0][d], a1 = Qs[pm0 + 1][d];
            float b0 = KVs[p_tx][d], b1 = KVs[p_tx + 16][d];
            p00 += a0 * b0; p01 += a0 * b1;
            p10 += a1 * b0; p11 += a1 * b1;
        }
        const int mg0 = mt * 32 + pm0, mg1 = mg0 + 1;
        const int ng0 = nt * 32 + p_tx, ng1 = nt * 32 + p_tx + 16;
        Ps[pm0][p_tx]          = (mg0 >= ng0) ? p00 * expf(-s * (float)(mg0 - ng0)) : 0.0f;
        Ps[pm0][p_tx + 16]     = (mg0 >= ng1) ? p01 * expf(-s * (float)(mg0 - ng1)) : 0.0f;
        Ps[pm0 + 1][p_tx]      = (mg1 >= ng0) ? p10 * expf(-s * (float)(mg1 - ng0)) : 0.0f;
        Ps[pm0 + 1][p_tx + 16] = (mg1 >= ng1) ? p11 * expf(-s * (float)(mg1 - ng1)) : 0.0f;
        __syncthreads();

#pragma unroll
        for (int r = 0; r < 4; ++r) {
            int idx = t + r * 256;
            int nn = idx >> 5, d4 = (idx & 31) * 4;
            float4 v4 = *(const float4*)(qbase + 256 + (size_t)(nt * 32 + nn) * QKVW + d4);
            *(float4*)&KVs[nn][d4] = v4;
        }
        __syncthreads();

#pragma unroll 4
        for (int n = 0; n < 32; ++n) {
            float a0 = Ps[om0][n], a1 = Ps[om0 + 1][n];
            float4 v0 = *(const float4*)&KVs[n][e0];
            float4 v1 = *(const float4*)&KVs[n][e0 + 4];
            oacc[0][0] += a0 * v0.x; oacc[0][1] += a0 * v0.y;
            oacc[0][2] += a0 * v0.z; oacc[0][3] += a0 * v0.w;
            oacc[0][4] += a0 * v1.x; oacc[0][5] += a0 * v1.y;
            oacc[0][6] += a0 * v1.z; oacc[0][7] += a0 * v1.w;
            oacc[1][0] += a1 * v0.x; oacc[1][1] += a1 * v0.y;
            oacc[1][2] += a1 * v0.z; oacc[1][3] += a1 * v0.w;
            oacc[1][4] += a1 * v1.x; oacc[1][5] += a1 * v1.y;
            oacc[1][6] += a1 * v1.z; oacc[1][7] += a1 * v1.w;
        }
    }

    float* hbase = g_hidden + (size_t)(b * BLK + mt * 32) * INNER + h * HD;
#pragma unroll
    for (int i = 0; i < 2; ++i) {
        float* Hp = hbase + (size_t)(om0 + i) * INNER + e0;
        float4 o0 = *(float4*)Hp;
        float4 o1 = *(float4*)(Hp + 4);
        o0.x += oacc[i][0]; o0.y += oacc[i][1]; o0.z += oacc[i][2]; o0.w += oacc[i][3];
        o1.x += oacc[i][4]; o1.y += oacc[i][5]; o1.z += oacc[i][6]; o1.w += oacc[i][7];
        *(float4*)Hp       = o0;
        *(float4*)(Hp + 4) = o1;
    }
}

// ---------------- RMSNorm * weight * gate -> fp16 (for GEMM3) ----------------
__global__ __launch_bounds__(256)
void rmsnorm_gate(const float* __restrict__ nw)
{
    const int m = blockIdx.x;
    const int t = threadIdx.x;
    const float* hrow = g_hidden + (size_t)m * INNER;
    const float* grow = g_gate + (size_t)m * INNER;
    __half* orow = g_ghalf + (size_t)m * INNER;

    float ss = 0.0f;
    for (int i = t; i < INNER / 4; i += 256) {
        float4 h4 = *(const float4*)(hrow + i * 4);
        ss += h4.x * h4.x + h4.y * h4.y + h4.z * h4.z + h4.w * h4.w;
    }
    __shared__ float red[256];
    red[t] = ss;
    __syncthreads();
    for (int s2 = 128; s2 > 0; s2 >>= 1) {
        if (t < s2) red[t] += red[t + s2];
        __syncthreads();
    }
    const float rs = rsqrtf(red[0] / (float)INNER + EPS_RMS);

    for (int i = t; i < INNER / 4; i += 256) {
        float4 h4 = *(const float4*)(hrow + i * 4);
        float4 g4 = *(const float4*)(grow + i * 4);
        float4 w4 = *(const float4*)(nw + i * 4);
        __half2 o0 = __floats2half2_rn(g4.x * (h4.x * rs * w4.x),
                                       g4.y * (h4.y * rs * w4.y));
        __half2 o1 = __floats2half2_rn(g4.z * (h4.z * rs * w4.z),
                                       g4.w * (h4.w * rs * w4.w));
        uint2 o;
        o.x = *(uint32_t*)&o0; o.y = *(uint32_t*)&o1;
        *(uint2*)(orow + i * 4) = o;
    }
}

// ---------------- launcher ----------------
extern "C" void kernel_launch(void* const* d_in, const int* in_sizes, int n_in,
                              void* d_out, int out_size)
{
    (void)in_sizes; (void)n_in; (void)out_size;
    const float* x     = (const float*)d_in[0];
    const float* wqkv  = (const float*)d_in[1];
    const float* wgate = (const float*)d_in[2];
    const float* wout  = (const float*)d_in[3];
    const float* nw    = (const float*)d_in[4];
    const float* kvc   = (const float*)d_in[5];
    const float* slope = (const float*)d_in[6];
    float* out = (float*)d_out;

    float *p_qkv = nullptr, *p_gate = nullptr;
    __half *p_xh = nullptr, *p_wqkvh = nullptr, *p_wgateh = nullptr,
           *p_wouth = nullptr, *p_ghalf = nullptr;
    cudaGetSymbolAddress((void**)&p_qkv, g_qkv);
    cudaGetSymbolAddress((void**)&p_gate, g_gate);
    cudaGetSymbolAddress((void**)&p_xh, g_xh);
    cudaGetSymbolAddress((void**)&p_wqkvh, g_wqkvh);
    cudaGetSymbolAddress((void**)&p_wgateh, g_wgateh);
    cudaGetSymbolAddress((void**)&p_wouth, g_wouth);
    cudaGetSymbolAddress((void**)&p_ghalf, g_ghalf);

    cudaFuncSetAttribute(gemm_mma<EPI_SILU>, cudaFuncAttributeMaxDynamicSharedMemorySize, GEMM_SMEM);
    cudaFuncSetAttribute(gemm_mma<EPI_SIGM>, cudaFuncAttributeMaxDynamicSharedMemorySize, GEMM_SMEM);
    cudaFuncSetAttribute(gemm_mma<EPI_NONE>, cudaFuncAttributeMaxDynamicSharedMemorySize, GEMM_SMEM);

    // fp32 -> fp16 conversions
    cvt_f16_kernel<<<(SEQ * HDIM / 8 + 255) / 256, 256>>>(x, p_xh, SEQ * HDIM / 8);
    cvt_f16_kernel<<<(QKVW * HDIM / 8 + 255) / 256, 256>>>(wqkv, p_wqkvh, QKVW * HDIM / 8);
    cvt_f16_kernel<<<(INNER * HDIM / 8 + 255) / 256, 256>>>(wgate, p_wgateh, INNER * HDIM / 8);
    cvt_f16_kernel<<<(HDIM * INNER / 8 + 255) / 256, 256>>>(wout, p_wouth, HDIM * INNER / 8);

    // qkv = silu(x @ w_qkv^T)
    gemm_mma<EPI_SILU><<<dim3(QKVW / BN, SEQ / BM), NTHR, GEMM_SMEM>>>(p_xh, p_wqkvh, p_qkv, QKVW);
    // gate = sigmoid(x @ w_gate^T)
    gemm_mma<EPI_SIGM><<<dim3(INNER / BN, SEQ / BM), NTHR, GEMM_SMEM>>>(p_xh, p_wgateh, p_gate, INNER);

    // lightning attention (fp32)
    attn_kvblocks<<<dim3(NB, NH), 256>>>(slope);
    attn_scan<<<(NH * HD * HD) / 256, 256>>>(kvc, slope);
    attn_ointer<<<dim3(NB, NH), 512>>>(slope);
    attn_ointra<<<dim3(8, NB, NH), 256>>>(slope);

    // rmsnorm * weight * gate -> fp16
    rmsnorm_gate<<<SEQ, 256>>>(nw);

    // out = (gate * normed) @ w_out^T
    gemm_mma<EPI_NONE><<<dim3(HDIM / BN, SEQ / BM), NTHR, GEMM_SMEM>>>(p_ghalf, p_wouth, out, HDIM);
}